// round 1
// baseline (speedup 1.0000x reference)
#include <cuda_runtime.h>
#include <cstring>

#define B_  32
#define T_  4096
#define H_  256
#define S_  256
#define M_  (B_*T_)   // 131072 rows

// ---------------- scratch (static device globals; no allocation) ----------------
__device__ float g_u[(size_t)M_ * S_];   // u, then states in-place (128 MB)
__device__ float g_mu[M_];
__device__ float g_rs[M_];
__device__ float g_coeff[S_];

typedef unsigned long long u64;

// ---------------- packed f32x2 helpers (sm_103a) ----------------
__device__ __forceinline__ u64 dup2(float v){
    u64 r; asm("mov.b64 %0, {%1, %1};" : "=l"(r) : "f"(v)); return r;
}
__device__ __forceinline__ void dfma(u64 &d, u64 a, u64 b){
    asm("fma.rn.f32x2 %0, %1, %2, %0;" : "+l"(d) : "l"(a), "l"(b));
}
__device__ __forceinline__ float2 unpk(u64 v){
    float2 f; asm("mov.b64 {%0, %1}, %2;" : "=f"(f.x), "=f"(f.y) : "l"(v)); return f;
}

__device__ __forceinline__ float gelu_t(float v){
    // jax.nn.gelu default approximate=True (tanh form)
    float v3 = v * v * v;
    float t  = tanhf(0.7978845608028654f * (v + 0.044715f * v3));
    return 0.5f * v * (1.0f + t);
}

// ---------------- shared GEMM building blocks ----------------
// A_s layout: [K=256][68]  (68-stride padded, column-major tile: A_s[k*68 + m])
// B_s layout: [32][260]    (one 32-wide K chunk: B_s[kk*260 + n])
#define A_STRIDE 68
#define B_STRIDE 260
#define A_ELEMS  (256*A_STRIDE)   // 17408
#define B_ELEMS  (32*B_STRIDE)    // 8320

// Load one 32-wide K chunk of a [256][256] row-major weight W, transposed into B_s:
// B_s[kk][n] = W[n][ch*32 + kk].  Coalesced 128B global reads per row group.
__device__ __forceinline__ void load_bchunk(float* B_s, const float* __restrict__ W,
                                            int ch, int tid)
{
    int kk4 = tid & 7;        // which float4 along K (k = 4*kk4 .. +3)
    int sb  = tid >> 3;       // 0..31 base row (n)
    #pragma unroll
    for (int j = 0; j < 8; j++){
        int n = sb + 32*j;
        float4 wv = *(const float4*)(W + (size_t)n*256 + ch*32 + 4*kk4);
        float* d = B_s + (4*kk4)*B_STRIDE + n;
        d[0]            = wv.x;
        d[B_STRIDE]     = wv.y;
        d[2*B_STRIDE]   = wv.z;
        d[3*B_STRIDE]   = wv.w;
    }
}

// Accumulate 32 K-steps: thread tile = 16 rows (as 8 row-pairs) x 4 cols.
// A-loads are warp-uniform (broadcast), B-loads contiguous across the warp.
__device__ __forceinline__ void gemm_chunk(const float* __restrict__ Ab,
                                           const float* __restrict__ Bs,
                                           u64 c[8][4], int mm, int nn)
{
    #pragma unroll 8
    for (int kk = 0; kk < 32; kk++){
        const float* ar = Ab + kk*A_STRIDE + mm;
        ulonglong2 a01 = *(const ulonglong2*)(ar + 0);
        ulonglong2 a23 = *(const ulonglong2*)(ar + 4);
        ulonglong2 a45 = *(const ulonglong2*)(ar + 8);
        ulonglong2 a67 = *(const ulonglong2*)(ar + 12);
        float4 bv = *(const float4*)(Bs + kk*B_STRIDE + nn);
        u64 b0 = dup2(bv.x), b1 = dup2(bv.y), b2 = dup2(bv.z), b3 = dup2(bv.w);
        u64 av[8] = {a01.x, a01.y, a23.x, a23.y, a45.x, a45.y, a67.x, a67.y};
        #pragma unroll
        for (int i = 0; i < 8; i++){
            dfma(c[i][0], av[i], b0);
            dfma(c[i][1], av[i], b1);
            dfma(c[i][2], av[i], b2);
            dfma(c[i][3], av[i], b3);
        }
    }
}

// ---------------- K0: discretized coefficients ----------------
__global__ void k0_coeff(const float* __restrict__ a, const float* __restrict__ g,
                         const float* __restrict__ dt)
{
    int s = threadIdx.x;
    double d   = (double)dt[s];
    double sp  = log1p(exp(-fabs(d))) + fmax(d, 0.0);        // softplus
    double dts = sp + 1e-4;
    double gg  = (double)g[s];
    double spg = log1p(exp(-fabs(gg))) + fmax(gg, 0.0);
    double dec = exp(-2.0 * spg * dts);                      // damped: decay^2
    g_coeff[s] = (float)(dec * cos((double)a[s] * dts));
}

// ---------------- K1: LayerNorm + input projection (u = xn @ Win^T) ----------------
__global__ void __launch_bounds__(256, 2)
k1_ln_inproj(const float* __restrict__ x, const float* __restrict__ Win,
             const float* __restrict__ nw, const float* __restrict__ nb)
{
    extern __shared__ float sm[];
    float* A_s  = sm;
    float* B_s  = A_s + A_ELEMS;
    float* mu_s = B_s + B_ELEMS;
    float* rs_s = mu_s + 64;
    float* w_s  = rs_s + 64;
    float* b_s  = w_s + 256;

    int tid = threadIdx.x;
    int m0  = blockIdx.x * 64;

    w_s[tid] = nw[tid];
    b_s[tid] = nb[tid];

    int mr = tid >> 2, qq = tid & 3;   // 4 threads per row
    const float4* xrow = (const float4*)(x + (size_t)(m0 + mr) * H_);

    float s1 = 0.f, s2 = 0.f;
    #pragma unroll
    for (int j = 0; j < 16; j++){
        float4 v = xrow[qq + 4*j];
        s1 += v.x + v.y + v.z + v.w;
        s2 += v.x*v.x + v.y*v.y + v.z*v.z + v.w*v.w;
    }
    s1 += __shfl_xor_sync(0xffffffffu, s1, 1);
    s2 += __shfl_xor_sync(0xffffffffu, s2, 1);
    s1 += __shfl_xor_sync(0xffffffffu, s1, 2);
    s2 += __shfl_xor_sync(0xffffffffu, s2, 2);
    if (qq == 0){
        float mu  = s1 * (1.0f / H_);
        float var = s2 * (1.0f / H_) - mu * mu;
        float rs  = rsqrtf(var + 1e-5f);
        mu_s[mr] = mu; rs_s[mr] = rs;
        g_mu[m0 + mr] = mu; g_rs[m0 + mr] = rs;
    }
    __syncthreads();

    // transpose + normalize into A_s[k][m]
    {
        float mu = mu_s[mr], rs = rs_s[mr];
        #pragma unroll
        for (int j = 0; j < 16; j++){
            int c4 = qq + 4*j;
            float4 v = xrow[c4];
            int k = 4 * c4;
            A_s[(k+0)*A_STRIDE + mr] = (v.x - mu) * rs * w_s[k+0] + b_s[k+0];
            A_s[(k+1)*A_STRIDE + mr] = (v.y - mu) * rs * w_s[k+1] + b_s[k+1];
            A_s[(k+2)*A_STRIDE + mr] = (v.z - mu) * rs * w_s[k+2] + b_s[k+2];
            A_s[(k+3)*A_STRIDE + mr] = (v.w - mu) * rs * w_s[k+3] + b_s[k+3];
        }
    }
    __syncthreads();

    int tc = tid & 63, tr = tid >> 6;
    int mm = tr * 16, nn = tc * 4;
    u64 c[8][4];
    #pragma unroll
    for (int i = 0; i < 8; i++)
        #pragma unroll
        for (int j = 0; j < 4; j++) c[i][j] = 0ull;

    for (int ch = 0; ch < 8; ch++){
        load_bchunk(B_s, Win, ch, tid);
        __syncthreads();
        gemm_chunk(A_s + ch*32*A_STRIDE, B_s, c, mm, nn);
        __syncthreads();
    }

    #pragma unroll
    for (int i = 0; i < 8; i++){
        float2 f0 = unpk(c[i][0]), f1 = unpk(c[i][1]);
        float2 f2 = unpk(c[i][2]), f3 = unpk(c[i][3]);
        *(float4*)(g_u + (size_t)(m0 + mm + 2*i    )*S_ + nn) = make_float4(f0.x, f1.x, f2.x, f3.x);
        *(float4*)(g_u + (size_t)(m0 + mm + 2*i + 1)*S_ + nn) = make_float4(f0.y, f1.y, f2.y, f3.y);
    }
}

// ---------------- K2: diagonal linear recurrence (in-place on g_u) ----------------
__global__ void k2_scan(const float* __restrict__ state0, float* __restrict__ finOut)
{
    int s = blockIdx.x * 32 + threadIdx.x;   // 0..255
    int b = blockIdx.y;                      // 0..31
    float cf = g_coeff[s];
    float st = state0[b*S_ + s];
    float* p = g_u + (size_t)b * T_ * S_ + s;

    float pre[8];
    #pragma unroll
    for (int j = 0; j < 8; j++) pre[j] = __ldcg(p + (size_t)j * S_);

    for (int t0 = 0; t0 < T_; t0 += 8){
        float cur[8];
        #pragma unroll
        for (int j = 0; j < 8; j++) cur[j] = pre[j];
        if (t0 + 8 < T_){
            const float* pn = p + (size_t)(t0 + 8) * S_;
            #pragma unroll
            for (int j = 0; j < 8; j++) pre[j] = __ldcg(pn + (size_t)j * S_);
        }
        float* pw = p + (size_t)t0 * S_;
        #pragma unroll
        for (int j = 0; j < 8; j++){
            st = fmaf(cf, st, cur[j]);
            pw[(size_t)j * S_] = st;
        }
    }
    finOut[b*S_ + s] = st;
}

// ---------------- K3: readout GEMM + direct*xn + gelu + output GEMM + residual ----------------
__global__ void __launch_bounds__(256, 2)
k3_out(const float* __restrict__ x, const float* __restrict__ W2, const float* __restrict__ W3,
       const float* __restrict__ direct, const float* __restrict__ nw, const float* __restrict__ nb,
       const float* __restrict__ ob, float* __restrict__ y)
{
    extern __shared__ float sm[];
    float* A_s  = sm;
    float* B_s  = A_s + A_ELEMS;
    float* mu_s = B_s + B_ELEMS;
    float* rs_s = mu_s + 64;
    float* w_s  = rs_s + 64;
    float* b_s  = w_s + 256;
    float* d_s  = b_s + 256;
    float* o_s  = d_s + 256;

    int tid = threadIdx.x;
    int m0  = blockIdx.x * 64;

    w_s[tid] = nw[tid]; b_s[tid] = nb[tid];
    d_s[tid] = direct[tid]; o_s[tid] = ob[tid];
    if (tid < 64){ mu_s[tid] = g_mu[m0 + tid]; rs_s[tid] = g_rs[m0 + tid]; }

    // load states tile transposed into A_s
    int mr = tid >> 2, qq = tid & 3;
    const float4* srow = (const float4*)(g_u + (size_t)(m0 + mr) * S_);
    #pragma unroll
    for (int j = 0; j < 16; j++){
        int c4 = qq + 4*j;
        float4 v = srow[c4];
        int k = 4 * c4;
        A_s[(k+0)*A_STRIDE + mr] = v.x;
        A_s[(k+1)*A_STRIDE + mr] = v.y;
        A_s[(k+2)*A_STRIDE + mr] = v.z;
        A_s[(k+3)*A_STRIDE + mr] = v.w;
    }
    __syncthreads();

    int tc = tid & 63, tr = tid >> 6;
    int mm = tr * 16, nn = tc * 4;

    u64 c[8][4];
    #pragma unroll
    for (int i = 0; i < 8; i++)
        #pragma unroll
        for (int j = 0; j < 4; j++) c[i][j] = 0ull;

    // GEMM2: mixed = states @ W2^T
    for (int ch = 0; ch < 8; ch++){
        load_bchunk(B_s, W2, ch, tid);
        __syncthreads();
        gemm_chunk(A_s + ch*32*A_STRIDE, B_s, c, mm, nn);
        __syncthreads();
    }

    // epilogue 2: + direct*x_norm, gelu, write transposed back into A_s
    #pragma unroll
    for (int i = 0; i < 8; i++){
        int r0 = mm + 2*i, r1 = r0 + 1;
        float4 xv0 = *(const float4*)(x + (size_t)(m0 + r0)*H_ + nn);
        float4 xv1 = *(const float4*)(x + (size_t)(m0 + r1)*H_ + nn);
        float xa0[4] = {xv0.x, xv0.y, xv0.z, xv0.w};
        float xa1[4] = {xv1.x, xv1.y, xv1.z, xv1.w};
        float mu0 = mu_s[r0], rv0 = rs_s[r0];
        float mu1 = mu_s[r1], rv1 = rs_s[r1];
        #pragma unroll
        for (int j = 0; j < 4; j++){
            int h = nn + j;
            float2 cc = unpk(c[i][j]);
            float xn0 = (xa0[j] - mu0) * rv0 * w_s[h] + b_s[h];
            float xn1 = (xa1[j] - mu1) * rv1 * w_s[h] + b_s[h];
            A_s[h*A_STRIDE + r0] = gelu_t(cc.x + d_s[h] * xn0);
            A_s[h*A_STRIDE + r1] = gelu_t(cc.y + d_s[h] * xn1);
        }
    }
    #pragma unroll
    for (int i = 0; i < 8; i++)
        #pragma unroll
        for (int j = 0; j < 4; j++) c[i][j] = 0ull;
    __syncthreads();

    // GEMM3: proj = gelu(mixed) @ W3^T
    for (int ch = 0; ch < 8; ch++){
        load_bchunk(B_s, W3, ch, tid);
        __syncthreads();
        gemm_chunk(A_s + ch*32*A_STRIDE, B_s, c, mm, nn);
        __syncthreads();
    }

    // epilogue 3: y = x + proj + out_b
    #pragma unroll
    for (int i = 0; i < 8; i++){
        int r0 = mm + 2*i, r1 = r0 + 1;
        float4 xv0 = *(const float4*)(x + (size_t)(m0 + r0)*H_ + nn);
        float4 xv1 = *(const float4*)(x + (size_t)(m0 + r1)*H_ + nn);
        float2 f0 = unpk(c[i][0]), f1 = unpk(c[i][1]);
        float2 f2 = unpk(c[i][2]), f3 = unpk(c[i][3]);
        float4 o0 = make_float4(xv0.x + f0.x + o_s[nn+0], xv0.y + f1.x + o_s[nn+1],
                                xv0.z + f2.x + o_s[nn+2], xv0.w + f3.x + o_s[nn+3]);
        float4 o1 = make_float4(xv1.x + f0.y + o_s[nn+0], xv1.y + f1.y + o_s[nn+1],
                                xv1.z + f2.y + o_s[nn+2], xv1.w + f3.y + o_s[nn+3]);
        *(float4*)(y + (size_t)(m0 + r0)*H_ + nn) = o0;
        *(float4*)(y + (size_t)(m0 + r1)*H_ + nn) = o1;
    }
}

// ---------------- launcher ----------------
extern "C" void kernel_launch(void* const* d_in, const int* in_sizes, int n_in,
                              void* d_out, int out_size)
{
    const float* x   = (const float*)d_in[0];   // [B,T,H]
    const float* st0 = (const float*)d_in[1];   // [B,S]
    const float* Win = (const float*)d_in[2];   // [S,H]
    const float* W2  = (const float*)d_in[3];   // [H,S]
    const float* dir = (const float*)d_in[4];   // [H]
    const float* ad  = (const float*)d_in[5];   // [S]
    const float* gd  = (const float*)d_in[6];   // [S]
    const float* dt  = (const float*)d_in[7];   // [S]
    const float* nw  = (const float*)d_in[8];   // [H]
    const float* nb  = (const float*)d_in[9];   // [H]
    const float* W3  = (const float*)d_in[10];  // [H,H]
    const float* ob  = (const float*)d_in[11];  // [H]

    float* y   = (float*)d_out;                 // [B,T,H]
    float* fin = y + (size_t)M_ * H_;           // [B,S] final state

    const int SMEM1 = (A_ELEMS + B_ELEMS + 64 + 64 + 256 + 256) * 4;
    const int SMEM3 = (A_ELEMS + B_ELEMS + 64 + 64 + 256 + 256 + 256 + 256) * 4;
    cudaFuncSetAttribute(k1_ln_inproj, cudaFuncAttributeMaxDynamicSharedMemorySize, SMEM1);
    cudaFuncSetAttribute(k3_out,       cudaFuncAttributeMaxDynamicSharedMemorySize, SMEM3);

    k0_coeff<<<1, 256>>>(ad, gd, dt);
    k1_ln_inproj<<<M_/64, 256, SMEM1>>>(x, Win, nw, nb);
    k2_scan<<<dim3(8, 32), 32>>>(st0, fin);
    k3_out<<<M_/64, 256, SMEM3>>>(x, W2, W3, dir, nw, nb, ob, y);
}

// round 3
// speedup vs baseline: 1.0073x; 1.0073x over previous
#include <cuda_runtime.h>
#include <cstring>

#define B_  32
#define T_  4096
#define H_  256
#define S_  256
#define M_  (B_*T_)   // 131072 rows

// ---------------- scratch (static device globals; no allocation) ----------------
__device__ float g_u[(size_t)M_ * S_];   // u, then states in-place (128 MB)
__device__ float g_mu[M_];
__device__ float g_rs[M_];
__device__ float g_coeff[S_];

typedef unsigned long long u64;

// ---------------- packed f32x2 helpers (sm_103a) ----------------
__device__ __forceinline__ u64 dup2(float v){
    u64 r; asm("mov.b64 %0, {%1, %1};" : "=l"(r) : "f"(v)); return r;
}
__device__ __forceinline__ void dfma(u64 &d, u64 a, u64 b){
    asm("fma.rn.f32x2 %0, %1, %2, %0;" : "+l"(d) : "l"(a), "l"(b));
}
__device__ __forceinline__ float2 unpk(u64 v){
    float2 f; asm("mov.b64 {%0, %1}, %2;" : "=f"(f.x), "=f"(f.y) : "l"(v)); return f;
}

__device__ __forceinline__ float gelu_t(float v){
    // jax.nn.gelu default approximate=True (tanh form)
    float v3 = v * v * v;
    float t  = tanhf(0.7978845608028654f * (v + 0.044715f * v3));
    return 0.5f * v * (1.0f + t);
}

// ---------------- shared GEMM building blocks ----------------
// A_s layout: [K=256][68]  (68-stride padded, column-major tile: A_s[k*68 + m])
// B_s layout: [32][260]    (one 32-wide K chunk: B_s[kk*260 + n])
#define A_STRIDE 68
#define B_STRIDE 260
#define A_ELEMS  (256*A_STRIDE)   // 17408
#define B_ELEMS  (32*B_STRIDE)    // 8320

// Load one 32-wide K chunk of a [256][256] row-major weight W, transposed into B_s:
// B_s[kk][n] = W[n][ch*32 + kk].  Coalesced 128B global reads per row group.
__device__ __forceinline__ void load_bchunk(float* B_s, const float* __restrict__ W,
                                            int ch, int tid)
{
    int kk4 = tid & 7;        // which float4 along K (k = 4*kk4 .. +3)
    int sb  = tid >> 3;       // 0..31 base row (n)
    #pragma unroll
    for (int j = 0; j < 8; j++){
        int n = sb + 32*j;
        float4 wv = *(const float4*)(W + (size_t)n*256 + ch*32 + 4*kk4);
        float* d = B_s + (4*kk4)*B_STRIDE + n;
        d[0]            = wv.x;
        d[B_STRIDE]     = wv.y;
        d[2*B_STRIDE]   = wv.z;
        d[3*B_STRIDE]   = wv.w;
    }
}

// Accumulate 32 K-steps: thread tile = 16 rows (as 8 row-pairs) x 4 cols.
// A-loads are warp-uniform (broadcast), B-loads contiguous across the warp.
__device__ __forceinline__ void gemm_chunk(const float* __restrict__ Ab,
                                           const float* __restrict__ Bs,
                                           u64 c[8][4], int mm, int nn)
{
    #pragma unroll 8
    for (int kk = 0; kk < 32; kk++){
        const float* ar = Ab + kk*A_STRIDE + mm;
        ulonglong2 a01 = *(const ulonglong2*)(ar + 0);
        ulonglong2 a23 = *(const ulonglong2*)(ar + 4);
        ulonglong2 a45 = *(const ulonglong2*)(ar + 8);
        ulonglong2 a67 = *(const ulonglong2*)(ar + 12);
        float4 bv = *(const float4*)(Bs + kk*B_STRIDE + nn);
        u64 b0 = dup2(bv.x), b1 = dup2(bv.y), b2 = dup2(bv.z), b3 = dup2(bv.w);
        u64 av[8] = {a01.x, a01.y, a23.x, a23.y, a45.x, a45.y, a67.x, a67.y};
        #pragma unroll
        for (int i = 0; i < 8; i++){
            dfma(c[i][0], av[i], b0);
            dfma(c[i][1], av[i], b1);
            dfma(c[i][2], av[i], b2);
            dfma(c[i][3], av[i], b3);
        }
    }
}

// ---------------- K0: discretized coefficients ----------------
__global__ void k0_coeff(const float* __restrict__ a, const float* __restrict__ g,
                         const float* __restrict__ dt)
{
    int s = threadIdx.x;
    double d   = (double)dt[s];
    double sp  = log1p(exp(-fabs(d))) + fmax(d, 0.0);        // softplus
    double dts = sp + 1e-4;
    double gg  = (double)g[s];
    double spg = log1p(exp(-fabs(gg))) + fmax(gg, 0.0);
    double dec = exp(-2.0 * spg * dts);                      // damped: decay^2
    g_coeff[s] = (float)(dec * cos((double)a[s] * dts));
}

// ---------------- K1: LayerNorm + input projection (u = xn @ Win^T) ----------------
__global__ void __launch_bounds__(256, 2)
k1_ln_inproj(const float* __restrict__ x, const float* __restrict__ Win,
             const float* __restrict__ nw, const float* __restrict__ nb)
{
    extern __shared__ float sm[];
    float* A_s  = sm;
    float* B_s  = A_s + A_ELEMS;
    float* mu_s = B_s + B_ELEMS;
    float* rs_s = mu_s + 64;
    float* w_s  = rs_s + 64;
    float* b_s  = w_s + 256;

    int tid = threadIdx.x;
    int m0  = blockIdx.x * 64;

    w_s[tid] = nw[tid];
    b_s[tid] = nb[tid];

    int mr = tid >> 2, qq = tid & 3;   // 4 threads per row
    const float4* xrow = (const float4*)(x + (size_t)(m0 + mr) * H_);

    float s1 = 0.f, s2 = 0.f;
    #pragma unroll
    for (int j = 0; j < 16; j++){
        float4 v = xrow[qq + 4*j];
        s1 += v.x + v.y + v.z + v.w;
        s2 += v.x*v.x + v.y*v.y + v.z*v.z + v.w*v.w;
    }
    s1 += __shfl_xor_sync(0xffffffffu, s1, 1);
    s2 += __shfl_xor_sync(0xffffffffu, s2, 1);
    s1 += __shfl_xor_sync(0xffffffffu, s1, 2);
    s2 += __shfl_xor_sync(0xffffffffu, s2, 2);
    if (qq == 0){
        float mu  = s1 * (1.0f / H_);
        float var = s2 * (1.0f / H_) - mu * mu;
        float rs  = rsqrtf(var + 1e-5f);
        mu_s[mr] = mu; rs_s[mr] = rs;
        g_mu[m0 + mr] = mu; g_rs[m0 + mr] = rs;
    }
    __syncthreads();

    // transpose + normalize into A_s[k][m]
    {
        float mu = mu_s[mr], rs = rs_s[mr];
        #pragma unroll
        for (int j = 0; j < 16; j++){
            int c4 = qq + 4*j;
            float4 v = xrow[c4];
            int k = 4 * c4;
            A_s[(k+0)*A_STRIDE + mr] = (v.x - mu) * rs * w_s[k+0] + b_s[k+0];
            A_s[(k+1)*A_STRIDE + mr] = (v.y - mu) * rs * w_s[k+1] + b_s[k+1];
            A_s[(k+2)*A_STRIDE + mr] = (v.z - mu) * rs * w_s[k+2] + b_s[k+2];
            A_s[(k+3)*A_STRIDE + mr] = (v.w - mu) * rs * w_s[k+3] + b_s[k+3];
        }
    }
    __syncthreads();

    int tc = tid & 63, tr = tid >> 6;
    int mm = tr * 16, nn = tc * 4;
    u64 c[8][4];
    #pragma unroll
    for (int i = 0; i < 8; i++)
        #pragma unroll
        for (int j = 0; j < 4; j++) c[i][j] = 0ull;

    for (int ch = 0; ch < 8; ch++){
        load_bchunk(B_s, Win, ch, tid);
        __syncthreads();
        gemm_chunk(A_s + ch*32*A_STRIDE, B_s, c, mm, nn);
        __syncthreads();
    }

    #pragma unroll
    for (int i = 0; i < 8; i++){
        float2 f0 = unpk(c[i][0]), f1 = unpk(c[i][1]);
        float2 f2 = unpk(c[i][2]), f3 = unpk(c[i][3]);
        *(float4*)(g_u + (size_t)(m0 + mm + 2*i    )*S_ + nn) = make_float4(f0.x, f1.x, f2.x, f3.x);
        *(float4*)(g_u + (size_t)(m0 + mm + 2*i + 1)*S_ + nn) = make_float4(f0.y, f1.y, f2.y, f3.y);
    }
}

// ---------------- K2: diagonal linear recurrence (in-place on g_u) ----------------
__global__ void k2_scan(const float* __restrict__ state0, float* __restrict__ finOut)
{
    int s = blockIdx.x * 32 + threadIdx.x;   // 0..255
    int b = blockIdx.y;                      // 0..31
    float cf = g_coeff[s];
    float st = state0[b*S_ + s];
    float* p = g_u + (size_t)b * T_ * S_ + s;

    float pre[8];
    #pragma unroll
    for (int j = 0; j < 8; j++) pre[j] = __ldcg(p + (size_t)j * S_);

    for (int t0 = 0; t0 < T_; t0 += 8){
        float cur[8];
        #pragma unroll
        for (int j = 0; j < 8; j++) cur[j] = pre[j];
        if (t0 + 8 < T_){
            const float* pn = p + (size_t)(t0 + 8) * S_;
            #pragma unroll
            for (int j = 0; j < 8; j++) pre[j] = __ldcg(pn + (size_t)j * S_);
        }
        float* pw = p + (size_t)t0 * S_;
        #pragma unroll
        for (int j = 0; j < 8; j++){
            st = fmaf(cf, st, cur[j]);
            pw[(size_t)j * S_] = st;
        }
    }
    finOut[b*S_ + s] = st;
}

// ---------------- K3: readout GEMM + direct*xn + gelu + output GEMM + residual ----------------
__global__ void __launch_bounds__(256, 2)
k3_out(const float* __restrict__ x, const float* __restrict__ W2, const float* __restrict__ W3,
       const float* __restrict__ direct, const float* __restrict__ nw, const float* __restrict__ nb,
       const float* __restrict__ ob, float* __restrict__ y)
{
    extern __shared__ float sm[];
    float* A_s  = sm;
    float* B_s  = A_s + A_ELEMS;
    float* mu_s = B_s + B_ELEMS;
    float* rs_s = mu_s + 64;
    float* w_s  = rs_s + 64;
    float* b_s  = w_s + 256;
    float* d_s  = b_s + 256;
    float* o_s  = d_s + 256;

    int tid = threadIdx.x;
    int m0  = blockIdx.x * 64;

    w_s[tid] = nw[tid]; b_s[tid] = nb[tid];
    d_s[tid] = direct[tid]; o_s[tid] = ob[tid];
    if (tid < 64){ mu_s[tid] = g_mu[m0 + tid]; rs_s[tid] = g_rs[m0 + tid]; }

    // load states tile transposed into A_s
    int mr = tid >> 2, qq = tid & 3;
    const float4* srow = (const float4*)(g_u + (size_t)(m0 + mr) * S_);
    #pragma unroll
    for (int j = 0; j < 16; j++){
        int c4 = qq + 4*j;
        float4 v = srow[c4];
        int k = 4 * c4;
        A_s[(k+0)*A_STRIDE + mr] = v.x;
        A_s[(k+1)*A_STRIDE + mr] = v.y;
        A_s[(k+2)*A_STRIDE + mr] = v.z;
        A_s[(k+3)*A_STRIDE + mr] = v.w;
    }
    __syncthreads();

    int tc = tid & 63, tr = tid >> 6;
    int mm = tr * 16, nn = tc * 4;

    u64 c[8][4];
    #pragma unroll
    for (int i = 0; i < 8; i++)
        #pragma unroll
        for (int j = 0; j < 4; j++) c[i][j] = 0ull;

    // GEMM2: mixed = states @ W2^T
    for (int ch = 0; ch < 8; ch++){
        load_bchunk(B_s, W2, ch, tid);
        __syncthreads();
        gemm_chunk(A_s + ch*32*A_STRIDE, B_s, c, mm, nn);
        __syncthreads();
    }

    // epilogue 2: + direct*x_norm, gelu, write transposed back into A_s
    #pragma unroll
    for (int i = 0; i < 8; i++){
        int r0 = mm + 2*i, r1 = r0 + 1;
        float4 xv0 = *(const float4*)(x + (size_t)(m0 + r0)*H_ + nn);
        float4 xv1 = *(const float4*)(x + (size_t)(m0 + r1)*H_ + nn);
        float xa0[4] = {xv0.x, xv0.y, xv0.z, xv0.w};
        float xa1[4] = {xv1.x, xv1.y, xv1.z, xv1.w};
        float mu0 = mu_s[r0], rv0 = rs_s[r0];
        float mu1 = mu_s[r1], rv1 = rs_s[r1];
        #pragma unroll
        for (int j = 0; j < 4; j++){
            int h = nn + j;
            float2 cc = unpk(c[i][j]);
            float xn0 = (xa0[j] - mu0) * rv0 * w_s[h] + b_s[h];
            float xn1 = (xa1[j] - mu1) * rv1 * w_s[h] + b_s[h];
            A_s[h*A_STRIDE + r0] = gelu_t(cc.x + d_s[h] * xn0);
            A_s[h*A_STRIDE + r1] = gelu_t(cc.y + d_s[h] * xn1);
        }
    }
    #pragma unroll
    for (int i = 0; i < 8; i++)
        #pragma unroll
        for (int j = 0; j < 4; j++) c[i][j] = 0ull;
    __syncthreads();

    // GEMM3: proj = gelu(mixed) @ W3^T
    for (int ch = 0; ch < 8; ch++){
        load_bchunk(B_s, W3, ch, tid);
        __syncthreads();
        gemm_chunk(A_s + ch*32*A_STRIDE, B_s, c, mm, nn);
        __syncthreads();
    }

    // epilogue 3: y = x + proj + out_b
    #pragma unroll
    for (int i = 0; i < 8; i++){
        int r0 = mm + 2*i, r1 = r0 + 1;
        float4 xv0 = *(const float4*)(x + (size_t)(m0 + r0)*H_ + nn);
        float4 xv1 = *(const float4*)(x + (size_t)(m0 + r1)*H_ + nn);
        float2 f0 = unpk(c[i][0]), f1 = unpk(c[i][1]);
        float2 f2 = unpk(c[i][2]), f3 = unpk(c[i][3]);
        float4 o0 = make_float4(xv0.x + f0.x + o_s[nn+0], xv0.y + f1.x + o_s[nn+1],
                                xv0.z + f2.x + o_s[nn+2], xv0.w + f3.x + o_s[nn+3]);
        float4 o1 = make_float4(xv1.x + f0.y + o_s[nn+0], xv1.y + f1.y + o_s[nn+1],
                                xv1.z + f2.y + o_s[nn+2], xv1.w + f3.y + o_s[nn+3]);
        *(float4*)(y + (size_t)(m0 + r0)*H_ + nn) = o0;
        *(float4*)(y + (size_t)(m0 + r1)*H_ + nn) = o1;
    }
}

// ---------------- launcher ----------------
extern "C" void kernel_launch(void* const* d_in, const int* in_sizes, int n_in,
                              void* d_out, int out_size)
{
    const float* x   = (const float*)d_in[0];   // [B,T,H]
    const float* st0 = (const float*)d_in[1];   // [B,S]
    const float* Win = (const float*)d_in[2];   // [S,H]
    const float* W2  = (const float*)d_in[3];   // [H,S]
    const float* dir = (const float*)d_in[4];   // [H]
    const float* ad  = (const float*)d_in[5];   // [S]
    const float* gd  = (const float*)d_in[6];   // [S]
    const float* dt  = (const float*)d_in[7];   // [S]
    const float* nw  = (const float*)d_in[8];   // [H]
    const float* nb  = (const float*)d_in[9];   // [H]
    const float* W3  = (const float*)d_in[10];  // [H,H]
    const float* ob  = (const float*)d_in[11];  // [H]

    float* y   = (float*)d_out;                 // [B,T,H]
    float* fin = y + (size_t)M_ * H_;           // [B,S] final state

    const int SMEM1 = (A_ELEMS + B_ELEMS + 64 + 64 + 256 + 256) * 4;
    const int SMEM3 = (A_ELEMS + B_ELEMS + 64 + 64 + 256 + 256 + 256 + 256) * 4;
    cudaFuncSetAttribute(k1_ln_inproj, cudaFuncAttributeMaxDynamicSharedMemorySize, SMEM1);
    cudaFuncSetAttribute(k3_out,       cudaFuncAttributeMaxDynamicSharedMemorySize, SMEM3);

    k0_coeff<<<1, 256>>>(ad, gd, dt);
    k1_ln_inproj<<<M_/64, 256, SMEM1>>>(x, Win, nw, nb);
    k2_scan<<<dim3(8, 32), 32>>>(st0, fin);
    k3_out<<<M_/64, 256, SMEM3>>>(x, W2, W3, dir, nw, nb, ob, y);
}

// round 5
// speedup vs baseline: 2.0085x; 1.9940x over previous
#include <cuda_runtime.h>
#include <cuda_bf16.h>

#define B_   32
#define T_   4096
#define H_   256
#define S_   256
#define M_   (B_*T_)      // 131072 rows
#define NSEG 64           // segments per batch (T/64)
#define SEGL 64           // segment length = k1 tile M

// A tile smem: [64 rows][264 bf16]  (row-major, 528B stride: conflict-free ldmatrix)
#define AST 264
// B tile smem: [256 n][40 bf16]     (80B stride: conflict-free ldmatrix)
#define BST 40

// ---------------- scratch (static device globals) ----------------
__device__ float g_u[(size_t)M_ * S_];     // segment-LOCAL states (written by k1)
__device__ float g_mu[M_];
__device__ float g_rs[M_];
__device__ float g_coeff[S_];
__device__ float g_P[SEGL * S_];           // P[j][s] = coeff[s]^(j+1)
__device__ float g_cl[B_ * NSEG * S_];     // local segment-end states
__device__ float g_ci[B_ * NSEG * S_];     // true state entering each segment
__device__ __align__(16) __nv_bfloat16 g_W1h[S_*H_], g_W1l[S_*H_];
__device__ __align__(16) __nv_bfloat16 g_W2h[H_*S_], g_W2l[H_*S_];
__device__ __align__(16) __nv_bfloat16 g_W3h[H_*H_], g_W3l[H_*H_];

typedef unsigned int u32;

// ---------------- small helpers ----------------
__device__ __forceinline__ unsigned sptr(const void* p){
    return (unsigned)__cvta_generic_to_shared(p);
}
__device__ __forceinline__ float bf_hi(float v){
    return __bfloat162float(__float2bfloat16(v));
}
// pack two floats to bf16x2: a -> low 16 bits (element at lower address), b -> high
__device__ __forceinline__ u32 pk2(float a, float b){
    __nv_bfloat16 ba = __float2bfloat16(a), bb = __float2bfloat16(b);
    unsigned short ua = *reinterpret_cast<unsigned short*>(&ba);
    unsigned short ub = *reinterpret_cast<unsigned short*>(&bb);
    return (u32)ua | ((u32)ub << 16);
}
__device__ __forceinline__ float gelu_t(float v){
    float v3 = v * v * v;
    float t  = tanhf(0.7978845608028654f * (v + 0.044715f * v3));
    return 0.5f * v * (1.0f + t);
}

__device__ __forceinline__ void ldsm4(u32 r[4], unsigned addr){
    asm volatile("ldmatrix.sync.aligned.m8n8.x4.shared.b16 {%0,%1,%2,%3}, [%4];"
        : "=r"(r[0]), "=r"(r[1]), "=r"(r[2]), "=r"(r[3]) : "r"(addr));
}
__device__ __forceinline__ void mma_bb(float c[4], const u32 a[4], u32 b0, u32 b1){
    asm volatile("mma.sync.aligned.m16n8k16.row.col.f32.bf16.bf16.f32 "
        "{%0,%1,%2,%3},{%4,%5,%6,%7},{%8,%9},{%0,%1,%2,%3};"
        : "+f"(c[0]), "+f"(c[1]), "+f"(c[2]), "+f"(c[3])
        : "r"(a[0]), "r"(a[1]), "r"(a[2]), "r"(a[3]), "r"(b0), "r"(b1));
}

// ---------------- bf16x3 GEMM core ----------------
// C[64m][256n] += A[64m][256k] @ W^T, W row-major [n][k], pre-split hi/lo bf16.
// 8 warps: warp grid 2(M)x4(N), warp tile 32x64. Accum c[mblk2][n8blk8][4].
// K streamed in 8 chunks of 32 through Bh/Bl smem.
__device__ __forceinline__ void gemm_bf16x3(
    const __nv_bfloat16* Ah, const __nv_bfloat16* Al,
    __nv_bfloat16* Bh, __nv_bfloat16* Bl,
    const __nv_bfloat16* __restrict__ Wh, const __nv_bfloat16* __restrict__ Wl,
    float c[2][8][4], int tid)
{
    const int lane = tid & 31;
    const int w    = tid >> 5;
    const int m0w  = (w >> 2) * 32;
    const int n0w  = (w & 3) * 64;
    const int k4   = tid & 7;      // B-load: which 4-elem group along k
    const int nb   = tid >> 3;     // B-load: base n row
    const int lrow = lane & 15;
    const int lc8  = (lane >> 4) * 8;

    const unsigned aAh = sptr(Ah + (m0w + lrow) * AST + lc8);
    const unsigned aAl = sptr(Al + (m0w + lrow) * AST + lc8);
    const unsigned aBh = sptr(Bh + (n0w + lrow) * BST + lc8);
    const unsigned aBl = sptr(Bl + (n0w + lrow) * BST + lc8);

    for (int ch = 0; ch < 8; ch++){
        // load W chunk [256n][32k] hi+lo (bf16 globals, L2-resident)
        #pragma unroll
        for (int j = 0; j < 8; j++){
            int n = nb + 32*j;
            uint2 vh = *(const uint2*)(Wh + n*256 + ch*32 + k4*4);
            uint2 vl = *(const uint2*)(Wl + n*256 + ch*32 + k4*4);
            *(uint2*)(Bh + n*BST + k4*4) = vh;
            *(uint2*)(Bl + n*BST + k4*4) = vl;
        }
        __syncthreads();

        #pragma unroll
        for (int ks = 0; ks < 2; ks++){
            const int kA2 = (ch*32 + ks*16) * 2;   // byte offset in A rows
            const int kB2 = (ks*16) * 2;           // byte offset in B rows
            u32 ah[2][4], al[2][4];
            ldsm4(ah[0], aAh + kA2);
            ldsm4(ah[1], aAh + 16*AST*2 + kA2);
            ldsm4(al[0], aAl + kA2);
            ldsm4(al[1], aAl + 16*AST*2 + kA2);
            #pragma unroll
            for (int g4 = 0; g4 < 4; g4++){        // 4 groups of n16
                u32 bh[4], bl[4];
                ldsm4(bh, aBh + g4*16*BST*2 + kB2);
                ldsm4(bl, aBl + g4*16*BST*2 + kB2);
                #pragma unroll
                for (int mb = 0; mb < 2; mb++){
                    // n-low block: B = {r0, r2}; n-high block: B = {r1, r3}
                    mma_bb(c[mb][g4*2  ], ah[mb], bh[0], bh[2]);
                    mma_bb(c[mb][g4*2  ], ah[mb], bl[0], bl[2]);
                    mma_bb(c[mb][g4*2  ], al[mb], bh[0], bh[2]);
                    mma_bb(c[mb][g4*2+1], ah[mb], bh[1], bh[3]);
                    mma_bb(c[mb][g4*2+1], ah[mb], bl[1], bl[3]);
                    mma_bb(c[mb][g4*2+1], al[mb], bh[1], bh[3]);
                }
            }
        }
        __syncthreads();
    }
}

// ---------------- K0a: coefficients + power table ----------------
__global__ void k0c(const float* __restrict__ a, const float* __restrict__ g,
                    const float* __restrict__ dt)
{
    int s = threadIdx.x;
    double d   = (double)dt[s];
    double sp  = log1p(exp(-fabs(d))) + fmax(d, 0.0);
    double dts = sp + 1e-4;
    double gg  = (double)g[s];
    double spg = log1p(exp(-fabs(gg))) + fmax(gg, 0.0);
    double cf  = exp(-2.0 * spg * dts) * cos((double)a[s] * dts);
    g_coeff[s] = (float)cf;
    double p = 1.0;
    for (int j = 0; j < SEGL; j++){ p *= cf; g_P[j*S_ + s] = (float)p; }
}

// ---------------- K0b: weight hi/lo split ----------------
__global__ void k0w(const float* __restrict__ W1, const float* __restrict__ W2,
                    const float* __restrict__ W3)
{
    int i = blockIdx.x * 256 + threadIdx.x;
    float w;
    __nv_bfloat16 h;
    w = W1[i]; h = __float2bfloat16(w); g_W1h[i] = h; g_W1l[i] = __float2bfloat16(w - __bfloat162float(h));
    w = W2[i]; h = __float2bfloat16(w); g_W2h[i] = h; g_W2l[i] = __float2bfloat16(w - __bfloat162float(h));
    w = W3[i]; h = __float2bfloat16(w); g_W3h[i] = h; g_W3l[i] = __float2bfloat16(w - __bfloat162float(h));
}

// ---------------- K1: LN + input GEMM + 64-step local scan ----------------
__global__ void __launch_bounds__(256, 2)
k1(const float* __restrict__ x, const float* __restrict__ nw, const float* __restrict__ nb)
{
    extern __shared__ __align__(16) char smraw[];
    __nv_bfloat16* Ah = (__nv_bfloat16*)smraw;
    __nv_bfloat16* Al = Ah + 64*AST;
    __nv_bfloat16* Bh = Al + 64*AST;
    __nv_bfloat16* Bl = Bh + 256*BST;
    float* w_s = (float*)(Bl + 256*BST);
    float* b_s = w_s + 256;
    float* U_s = (float*)smraw;           // overlay on A after GEMM (stride 260)

    const int tid = threadIdx.x;
    const int m0  = blockIdx.x * 64;
    w_s[tid] = nw[tid]; b_s[tid] = nb[tid];

    // --- LayerNorm (mu/rs via shuffle; 4 threads per row) ---
    const int mr = tid >> 2, qq = tid & 3;
    const float4* xrow = (const float4*)(x + (size_t)(m0 + mr) * H_);
    float s1 = 0.f, s2 = 0.f;
    #pragma unroll
    for (int j = 0; j < 16; j++){
        float4 v = xrow[qq + 4*j];
        s1 += v.x + v.y + v.z + v.w;
        s2 += v.x*v.x + v.y*v.y + v.z*v.z + v.w*v.w;
    }
    s1 += __shfl_xor_sync(0xffffffffu, s1, 1);
    s2 += __shfl_xor_sync(0xffffffffu, s2, 1);
    s1 += __shfl_xor_sync(0xffffffffu, s1, 2);
    s2 += __shfl_xor_sync(0xffffffffu, s2, 2);
    float mu  = s1 * (1.0f / H_);
    float var = s2 * (1.0f / H_) - mu * mu;
    float rs  = rsqrtf(var + 1e-5f);
    if (qq == 0){ g_mu[m0 + mr] = mu; g_rs[m0 + mr] = rs; }

    // *** make w_s/b_s visible to ALL threads before the normalize loop ***
    __syncthreads();

    // --- normalize + bf16 hi/lo split into A ---
    #pragma unroll
    for (int j = 0; j < 16; j++){
        int c0 = 4*(qq + 4*j);
        float4 v = xrow[qq + 4*j];
        float f0 = (v.x - mu) * rs * w_s[c0+0] + b_s[c0+0];
        float f1 = (v.y - mu) * rs * w_s[c0+1] + b_s[c0+1];
        float f2 = (v.z - mu) * rs * w_s[c0+2] + b_s[c0+2];
        float f3 = (v.w - mu) * rs * w_s[c0+3] + b_s[c0+3];
        uint2 ph, pl;
        ph.x = pk2(f0, f1); ph.y = pk2(f2, f3);
        pl.x = pk2(f0 - bf_hi(f0), f1 - bf_hi(f1));
        pl.y = pk2(f2 - bf_hi(f2), f3 - bf_hi(f3));
        *(uint2*)(Ah + mr*AST + c0) = ph;
        *(uint2*)(Al + mr*AST + c0) = pl;
    }
    // (first __syncthreads inside gemm makes A visible before ldmatrix)

    float c[2][8][4];
    #pragma unroll
    for (int i = 0; i < 2; i++)
        #pragma unroll
        for (int j = 0; j < 8; j++)
            #pragma unroll
            for (int q = 0; q < 4; q++) c[i][j][q] = 0.f;

    gemm_bf16x3(Ah, Al, Bh, Bl, g_W1h, g_W1l, c, tid);

    // --- dump u into smem scratch (gemm ended with syncthreads) ---
    {
        const int lane = tid & 31, w = tid >> 5;
        const int m0w = (w >> 2) * 32, n0w = (w & 3) * 64;
        const int gg = lane >> 2, tg = lane & 3;
        #pragma unroll
        for (int mb = 0; mb < 2; mb++)
            #pragma unroll
            for (int n8 = 0; n8 < 8; n8++){
                int r0 = m0w + mb*16 + gg;
                int cc = n0w + n8*8 + 2*tg;
                *(float2*)(U_s + r0*260 + cc)     = make_float2(c[mb][n8][0], c[mb][n8][1]);
                *(float2*)(U_s + (r0+8)*260 + cc) = make_float2(c[mb][n8][2], c[mb][n8][3]);
            }
    }
    __syncthreads();

    // --- 64-step local scan along rows, one column per thread ---
    {
        int s = tid;
        float cf = g_coeff[s];
        float st = 0.f;
        float pre[8];
        #pragma unroll
        for (int j = 0; j < 8; j++) pre[j] = U_s[j*260 + s];
        for (int r0 = 0; r0 < 64; r0 += 8){
            float cur[8];
            #pragma unroll
            for (int j = 0; j < 8; j++) cur[j] = pre[j];
            if (r0 + 8 < 64){
                #pragma unroll
                for (int j = 0; j < 8; j++) pre[j] = U_s[(r0+8+j)*260 + s];
            }
            #pragma unroll
            for (int j = 0; j < 8; j++){
                st = fmaf(cf, st, cur[j]);
                U_s[(r0+j)*260 + s] = st;
            }
        }
        int b = m0 >> 12, seg = (m0 >> 6) & 63;
        g_cl[(b*NSEG + seg)*S_ + s] = st;
    }
    __syncthreads();

    // --- write local states to global ---
    #pragma unroll
    for (int j = 0; j < 16; j++){
        int c0 = 4*(qq + 4*j);
        float4 v = *(const float4*)(U_s + mr*260 + c0);
        *(float4*)(g_u + (size_t)(m0 + mr)*S_ + c0) = v;
    }
}

// ---------------- K2b: carry chain across segments ----------------
__global__ void k2b(const float* __restrict__ st0, float* __restrict__ fin)
{
    int s = threadIdx.x, b = blockIdx.x;
    float c64 = g_P[(SEGL-1)*S_ + s];    // coeff^64
    float ci  = st0[b*S_ + s];
    const float* cl = g_cl + (size_t)b*NSEG*S_ + s;
    float*       cp = g_ci + (size_t)b*NSEG*S_ + s;
    float nxt = cl[0];
    #pragma unroll 1
    for (int seg = 0; seg < NSEG; seg++){
        float cur = nxt;
        if (seg + 1 < NSEG) nxt = cl[(seg+1)*S_];
        cp[seg*S_] = ci;
        ci = fmaf(c64, ci, cur);
    }
    fin[b*S_ + s] = ci;
}

// ---------------- K3: readout GEMM + gelu + output GEMM + residual ----------------
__global__ void __launch_bounds__(256, 2)
k3(const float* __restrict__ x, const float* __restrict__ nw, const float* __restrict__ nb,
   const float* __restrict__ dir, const float* __restrict__ ob, float* __restrict__ y)
{
    extern __shared__ __align__(16) char smraw[];
    __nv_bfloat16* Ah = (__nv_bfloat16*)smraw;
    __nv_bfloat16* Al = Ah + 64*AST;
    __nv_bfloat16* Bh = Al + 64*AST;
    __nv_bfloat16* Bl = Bh + 256*BST;
    float* w_s  = (float*)(Bl + 256*BST);
    float* b_s  = w_s + 256;
    float* d_s  = b_s + 256;
    float* o_s  = d_s + 256;
    float* mu_s = o_s + 256;
    float* rs_s = mu_s + 64;

    const int tid = threadIdx.x;
    const int m0  = blockIdx.x * 64;
    w_s[tid] = nw[tid]; b_s[tid] = nb[tid];
    d_s[tid] = dir[tid]; o_s[tid] = ob[tid];
    if (tid < 64){ mu_s[tid] = g_mu[m0 + tid]; rs_s[tid] = g_rs[m0 + tid]; }
    // (these are first read in epilogue 2, after gemm's internal barriers)

    // --- load states tile: local + P[j]*carry, split hi/lo into A ---
    const int mr = tid >> 2, qq = tid & 3;
    {
        int b = m0 >> 12, seg = (m0 >> 6) & 63;
        const float* lrow = g_u + (size_t)(m0 + mr) * S_;
        const float* Prow = g_P + mr * S_;                 // j == row-in-tile
        const float* crow = g_ci + (size_t)(b*NSEG + seg) * S_;
        #pragma unroll
        for (int j = 0; j < 16; j++){
            int c0 = 4*(qq + 4*j);
            float4 lv = *(const float4*)(lrow + c0);
            float4 pv = *(const float4*)(Prow + c0);
            float4 cv = *(const float4*)(crow + c0);
            float f0 = fmaf(pv.x, cv.x, lv.x);
            float f1 = fmaf(pv.y, cv.y, lv.y);
            float f2 = fmaf(pv.z, cv.z, lv.z);
            float f3 = fmaf(pv.w, cv.w, lv.w);
            uint2 ph, pl;
            ph.x = pk2(f0, f1); ph.y = pk2(f2, f3);
            pl.x = pk2(f0 - bf_hi(f0), f1 - bf_hi(f1));
            pl.y = pk2(f2 - bf_hi(f2), f3 - bf_hi(f3));
            *(uint2*)(Ah + mr*AST + c0) = ph;
            *(uint2*)(Al + mr*AST + c0) = pl;
        }
    }

    float c[2][8][4];
    #pragma unroll
    for (int i = 0; i < 2; i++)
        #pragma unroll
        for (int j = 0; j < 8; j++)
            #pragma unroll
            for (int q = 0; q < 4; q++) c[i][j][q] = 0.f;

    // GEMM2: mixed = states @ W2^T
    gemm_bf16x3(Ah, Al, Bh, Bl, g_W2h, g_W2l, c, tid);

    // --- epilogue 2: + direct*x_norm, gelu, re-split into A ---
    const int lane = tid & 31, w = tid >> 5;
    const int m0w = (w >> 2) * 32, n0w = (w & 3) * 64;
    const int gg = lane >> 2, tg = lane & 3;
    #pragma unroll
    for (int mb = 0; mb < 2; mb++)
        #pragma unroll
        for (int n8 = 0; n8 < 8; n8++){
            int cc = n0w + n8*8 + 2*tg;
            float dw0 = d_s[cc], dw1 = d_s[cc+1];
            float ww0 = w_s[cc], ww1 = w_s[cc+1];
            float bb0 = b_s[cc], bb1 = b_s[cc+1];
            #pragma unroll
            for (int half = 0; half < 2; half++){
                int r = m0w + mb*16 + gg + half*8;
                float2 xv = *(const float2*)(x + (size_t)(m0 + r)*H_ + cc);
                float muv = mu_s[r], rsv = rs_s[r];
                float xn0 = (xv.x - muv) * rsv * ww0 + bb0;
                float xn1 = (xv.y - muv) * rsv * ww1 + bb1;
                float v0 = gelu_t(c[mb][n8][half*2+0] + dw0 * xn0);
                float v1 = gelu_t(c[mb][n8][half*2+1] + dw1 * xn1);
                *(u32*)(Ah + r*AST + cc) = pk2(v0, v1);
                *(u32*)(Al + r*AST + cc) = pk2(v0 - bf_hi(v0), v1 - bf_hi(v1));
            }
        }
    #pragma unroll
    for (int i = 0; i < 2; i++)
        #pragma unroll
        for (int j = 0; j < 8; j++)
            #pragma unroll
            for (int q = 0; q < 4; q++) c[i][j][q] = 0.f;

    // GEMM3: proj = gelu(mixed) @ W3^T
    gemm_bf16x3(Ah, Al, Bh, Bl, g_W3h, g_W3l, c, tid);

    // --- epilogue 3: y = x + proj + out_b ---
    #pragma unroll
    for (int mb = 0; mb < 2; mb++)
        #pragma unroll
        for (int n8 = 0; n8 < 8; n8++){
            int cc = n0w + n8*8 + 2*tg;
            float oo0 = o_s[cc], oo1 = o_s[cc+1];
            #pragma unroll
            for (int half = 0; half < 2; half++){
                int r = m0w + mb*16 + gg + half*8;
                float2 xv = *(const float2*)(x + (size_t)(m0 + r)*H_ + cc);
                float2 out;
                out.x = xv.x + c[mb][n8][half*2+0] + oo0;
                out.y = xv.y + c[mb][n8][half*2+1] + oo1;
                *(float2*)(y + (size_t)(m0 + r)*H_ + cc) = out;
            }
        }
}

// ---------------- launcher ----------------
extern "C" void kernel_launch(void* const* d_in, const int* in_sizes, int n_in,
                              void* d_out, int out_size)
{
    const float* x   = (const float*)d_in[0];   // [B,T,H]
    const float* st0 = (const float*)d_in[1];   // [B,S]
    const float* Win = (const float*)d_in[2];   // [S,H]
    const float* W2  = (const float*)d_in[3];   // [H,S]
    const float* dir = (const float*)d_in[4];   // [H]
    const float* ad  = (const float*)d_in[5];   // [S]
    const float* gd  = (const float*)d_in[6];   // [S]
    const float* dt  = (const float*)d_in[7];   // [S]
    const float* nw  = (const float*)d_in[8];   // [H]
    const float* nb  = (const float*)d_in[9];   // [H]
    const float* W3  = (const float*)d_in[10];  // [H,H]
    const float* ob  = (const float*)d_in[11];  // [H]

    float* y   = (float*)d_out;
    float* fin = y + (size_t)M_ * H_;

    const int SMEM1 = (64*AST*2 + 256*BST*2)*2 + (256+256)*4;
    const int SMEM3 = (64*AST*2 + 256*BST*2)*2 + (256*4 + 64*2)*4;
    cudaFuncSetAttribute(k1, cudaFuncAttributeMaxDynamicSharedMemorySize, SMEM1);
    cudaFuncSetAttribute(k3, cudaFuncAttributeMaxDynamicSharedMemorySize, SMEM3);

    k0c<<<1, 256>>>(ad, gd, dt);
    k0w<<<256, 256>>>(Win, W2, W3);
    k1<<<M_/64, 256, SMEM1>>>(x, nw, nb);
    k2b<<<B_, 256>>>(st0, fin);
    k3<<<M_/64, 256, SMEM3>>>(x, nw, nb, dir, ob, y);
}

// round 6
// speedup vs baseline: 2.3839x; 1.1869x over previous
#include <cuda_runtime.h>
#include <cuda_bf16.h>

#define B_   32
#define T_   4096
#define H_   256
#define S_   256
#define M_   (B_*T_)      // 131072 rows
#define TM_  128          // M tile / segment length
#define NSEG 32           // segments per batch (T/TM_)
#define SEGL 128

// A tile smem: [128 rows][264 bf16]  (row-major, 528B stride: conflict-free ldmatrix)
#define AST 264
// B tile smem: [256 n][40 bf16]      (80B stride: conflict-free ldmatrix)
#define BST 40

// ---------------- scratch (static device globals) ----------------
__device__ float g_u[(size_t)M_ * S_];     // segment-LOCAL states (written by k1)
__device__ float g_mu[M_];
__device__ float g_rs[M_];
__device__ float g_coeff[S_];
__device__ float g_P[SEGL * S_];           // P[j][s] = coeff[s]^(j+1)
__device__ float g_cl[B_ * NSEG * S_];     // local segment-end states
__device__ float g_ci[B_ * NSEG * S_];     // true state entering each segment
__device__ __align__(16) __nv_bfloat16 g_W1h[S_*H_], g_W1l[S_*H_];
__device__ __align__(16) __nv_bfloat16 g_W2h[H_*S_], g_W2l[H_*S_];
__device__ __align__(16) __nv_bfloat16 g_W3h[H_*H_], g_W3l[H_*H_];

typedef unsigned int u32;

// ---------------- small helpers ----------------
__device__ __forceinline__ unsigned sptr(const void* p){
    return (unsigned)__cvta_generic_to_shared(p);
}
__device__ __forceinline__ float bf_hi(float v){
    return __bfloat162float(__float2bfloat16(v));
}
// pack two floats to bf16x2: a -> low 16 bits (element at lower address), b -> high
__device__ __forceinline__ u32 pk2(float a, float b){
    __nv_bfloat16 ba = __float2bfloat16(a), bb = __float2bfloat16(b);
    unsigned short ua = *reinterpret_cast<unsigned short*>(&ba);
    unsigned short ub = *reinterpret_cast<unsigned short*>(&bb);
    return (u32)ua | ((u32)ub << 16);
}
__device__ __forceinline__ float gelu_t(float v){
    float v3 = v * v * v;
    float t  = tanhf(0.7978845608028654f * (v + 0.044715f * v3));
    return 0.5f * v * (1.0f + t);
}

__device__ __forceinline__ void ldsm4(u32 r[4], unsigned addr){
    asm volatile("ldmatrix.sync.aligned.m8n8.x4.shared.b16 {%0,%1,%2,%3}, [%4];"
        : "=r"(r[0]), "=r"(r[1]), "=r"(r[2]), "=r"(r[3]) : "r"(addr));
}
__device__ __forceinline__ void mma_bb(float c[4], const u32 a[4], u32 b0, u32 b1){
    asm volatile("mma.sync.aligned.m16n8k16.row.col.f32.bf16.bf16.f32 "
        "{%0,%1,%2,%3},{%4,%5,%6,%7},{%8,%9},{%0,%1,%2,%3};"
        : "+f"(c[0]), "+f"(c[1]), "+f"(c[2]), "+f"(c[3])
        : "r"(a[0]), "r"(a[1]), "r"(a[2]), "r"(a[3]), "r"(b0), "r"(b1));
}

// ---------------- bf16x3 GEMM core ----------------
// C[128m][256n] += A[128m][256k] @ W^T, W row-major [n][k], pre-split hi/lo bf16.
// 16 warps: warp grid 4(M)x4(N), warp tile 32x64. Accum c[mblk2][n8blk8][4].
// K streamed in 8 chunks of 32 through Bh/Bl smem; next chunk register-prefetched
// so L2 latency hides behind the mma compute of the current chunk.
__device__ __forceinline__ void gemm_bf16x3(
    const __nv_bfloat16* Ah, const __nv_bfloat16* Al,
    __nv_bfloat16* Bh, __nv_bfloat16* Bl,
    const __nv_bfloat16* __restrict__ Wh, const __nv_bfloat16* __restrict__ Wl,
    float c[2][8][4], int tid)
{
    const int lane = tid & 31;
    const int w    = tid >> 5;            // 0..15
    const int m0w  = (w >> 2) * 32;
    const int n0w  = (w & 3) * 64;
    const int k4   = tid & 7;             // B-load: which 4-elem group along k
    const int nb   = tid >> 3;            // B-load: base n row (0..63)
    const int lrow = lane & 15;
    const int lc8  = (lane >> 4) * 8;

    const unsigned aAh = sptr(Ah + (m0w + lrow) * AST + lc8);
    const unsigned aAl = sptr(Al + (m0w + lrow) * AST + lc8);
    const unsigned aBh = sptr(Bh + (n0w + lrow) * BST + lc8);
    const unsigned aBl = sptr(Bl + (n0w + lrow) * BST + lc8);

    // prefetch chunk 0 into registers
    uint2 ph[4], pl4[4];
    #pragma unroll
    for (int j = 0; j < 4; j++){
        int n = nb + 64*j;
        ph[j]  = *(const uint2*)(Wh + n*256 + k4*4);
        pl4[j] = *(const uint2*)(Wl + n*256 + k4*4);
    }

    for (int ch = 0; ch < 8; ch++){
        __syncthreads();   // prev compute done (B smem reusable); A visible (1st iter)
        #pragma unroll
        for (int j = 0; j < 4; j++){
            int n = nb + 64*j;
            *(uint2*)(Bh + n*BST + k4*4) = ph[j];
            *(uint2*)(Bl + n*BST + k4*4) = pl4[j];
        }
        __syncthreads();   // B chunk visible
        if (ch < 7){       // issue next chunk's loads; they retire during compute
            #pragma unroll
            for (int j = 0; j < 4; j++){
                int n = nb + 64*j;
                ph[j]  = *(const uint2*)(Wh + n*256 + (ch+1)*32 + k4*4);
                pl4[j] = *(const uint2*)(Wl + n*256 + (ch+1)*32 + k4*4);
            }
        }

        #pragma unroll
        for (int ks = 0; ks < 2; ks++){
            const int kA2 = (ch*32 + ks*16) * 2;   // byte offset in A rows
            const int kB2 = (ks*16) * 2;           // byte offset in B rows
            u32 ah[2][4], al[2][4];
            ldsm4(ah[0], aAh + kA2);
            ldsm4(ah[1], aAh + 16*AST*2 + kA2);
            ldsm4(al[0], aAl + kA2);
            ldsm4(al[1], aAl + 16*AST*2 + kA2);
            #pragma unroll
            for (int g4 = 0; g4 < 4; g4++){        // 4 groups of n16
                u32 bh[4], bl[4];
                ldsm4(bh, aBh + g4*16*BST*2 + kB2);
                ldsm4(bl, aBl + g4*16*BST*2 + kB2);
                #pragma unroll
                for (int mb = 0; mb < 2; mb++){
                    // n-low block: B = {r0, r2}; n-high block: B = {r1, r3}
                    mma_bb(c[mb][g4*2  ], ah[mb], bh[0], bh[2]);
                    mma_bb(c[mb][g4*2  ], ah[mb], bl[0], bl[2]);
                    mma_bb(c[mb][g4*2  ], al[mb], bh[0], bh[2]);
                    mma_bb(c[mb][g4*2+1], ah[mb], bh[1], bh[3]);
                    mma_bb(c[mb][g4*2+1], ah[mb], bl[1], bl[3]);
                    mma_bb(c[mb][g4*2+1], al[mb], bh[1], bh[3]);
                }
            }
        }
    }
    __syncthreads();   // protect epilogue overlay writes into A (WAR across warps)
}

// ---------------- K0a: coefficients + power table ----------------
__global__ void k0c(const float* __restrict__ a, const float* __restrict__ g,
                    const float* __restrict__ dt)
{
    int s = threadIdx.x;
    double d   = (double)dt[s];
    double sp  = log1p(exp(-fabs(d))) + fmax(d, 0.0);
    double dts = sp + 1e-4;
    double gg  = (double)g[s];
    double spg = log1p(exp(-fabs(gg))) + fmax(gg, 0.0);
    double cf  = exp(-2.0 * spg * dts) * cos((double)a[s] * dts);
    g_coeff[s] = (float)cf;
    double p = 1.0;
    for (int j = 0; j < SEGL; j++){ p *= cf; g_P[j*S_ + s] = (float)p; }
}

// ---------------- K0b: weight hi/lo split ----------------
__global__ void k0w(const float* __restrict__ W1, const float* __restrict__ W2,
                    const float* __restrict__ W3)
{
    int i = blockIdx.x * 256 + threadIdx.x;
    float w;
    __nv_bfloat16 h;
    w = W1[i]; h = __float2bfloat16(w); g_W1h[i] = h; g_W1l[i] = __float2bfloat16(w - __bfloat162float(h));
    w = W2[i]; h = __float2bfloat16(w); g_W2h[i] = h; g_W2l[i] = __float2bfloat16(w - __bfloat162float(h));
    w = W3[i]; h = __float2bfloat16(w); g_W3h[i] = h; g_W3l[i] = __float2bfloat16(w - __bfloat162float(h));
}

// ---------------- K1: LN + input GEMM + 128-step local scan ----------------
__global__ void __launch_bounds__(512, 1)
k1(const float* __restrict__ x, const float* __restrict__ nw, const float* __restrict__ nb)
{
    extern __shared__ __align__(16) char smraw[];
    __nv_bfloat16* Ah = (__nv_bfloat16*)smraw;
    __nv_bfloat16* Al = Ah + TM_*AST;
    __nv_bfloat16* Bh = Al + TM_*AST;
    __nv_bfloat16* Bl = Bh + 256*BST;
    float* w_s = (float*)(Bl + 256*BST);
    float* b_s = w_s + 256;
    float* U_s = (float*)smraw;           // overlay on A after GEMM (stride 260)

    const int tid = threadIdx.x;
    const int m0  = blockIdx.x * TM_;
    if (tid < 256){ w_s[tid] = nw[tid]; b_s[tid] = nb[tid]; }

    // --- LayerNorm (mu/rs via shuffle; 4 threads per row) ---
    const int mr = tid >> 2, qq = tid & 3;     // mr 0..127
    const float4* xrow = (const float4*)(x + (size_t)(m0 + mr) * H_);
    float s1 = 0.f, s2 = 0.f;
    #pragma unroll
    for (int j = 0; j < 16; j++){
        float4 v = xrow[qq + 4*j];
        s1 += v.x + v.y + v.z + v.w;
        s2 += v.x*v.x + v.y*v.y + v.z*v.z + v.w*v.w;
    }
    s1 += __shfl_xor_sync(0xffffffffu, s1, 1);
    s2 += __shfl_xor_sync(0xffffffffu, s2, 1);
    s1 += __shfl_xor_sync(0xffffffffu, s1, 2);
    s2 += __shfl_xor_sync(0xffffffffu, s2, 2);
    float mu  = s1 * (1.0f / H_);
    float var = s2 * (1.0f / H_) - mu * mu;
    float rs  = rsqrtf(var + 1e-5f);
    if (qq == 0){ g_mu[m0 + mr] = mu; g_rs[m0 + mr] = rs; }

    // make w_s/b_s visible to ALL threads before the normalize loop
    __syncthreads();

    // --- normalize + bf16 hi/lo split into A ---
    #pragma unroll
    for (int j = 0; j < 16; j++){
        int c0 = 4*(qq + 4*j);
        float4 v = xrow[qq + 4*j];
        float f0 = (v.x - mu) * rs * w_s[c0+0] + b_s[c0+0];
        float f1 = (v.y - mu) * rs * w_s[c0+1] + b_s[c0+1];
        float f2 = (v.z - mu) * rs * w_s[c0+2] + b_s[c0+2];
        float f3 = (v.w - mu) * rs * w_s[c0+3] + b_s[c0+3];
        uint2 ph, pl;
        ph.x = pk2(f0, f1); ph.y = pk2(f2, f3);
        pl.x = pk2(f0 - bf_hi(f0), f1 - bf_hi(f1));
        pl.y = pk2(f2 - bf_hi(f2), f3 - bf_hi(f3));
        *(uint2*)(Ah + mr*AST + c0) = ph;
        *(uint2*)(Al + mr*AST + c0) = pl;
    }
    // (first __syncthreads inside gemm makes A visible before ldmatrix)

    float c[2][8][4];
    #pragma unroll
    for (int i = 0; i < 2; i++)
        #pragma unroll
        for (int j = 0; j < 8; j++)
            #pragma unroll
            for (int q = 0; q < 4; q++) c[i][j][q] = 0.f;

    gemm_bf16x3(Ah, Al, Bh, Bl, g_W1h, g_W1l, c, tid);

    // --- dump u into smem scratch (gemm ended with syncthreads) ---
    {
        const int lane = tid & 31, w = tid >> 5;
        const int m0w = (w >> 2) * 32, n0w = (w & 3) * 64;
        const int gg = lane >> 2, tg = lane & 3;
        #pragma unroll
        for (int mb = 0; mb < 2; mb++)
            #pragma unroll
            for (int n8 = 0; n8 < 8; n8++){
                int r0 = m0w + mb*16 + gg;
                int cc = n0w + n8*8 + 2*tg;
                *(float2*)(U_s + r0*260 + cc)     = make_float2(c[mb][n8][0], c[mb][n8][1]);
                *(float2*)(U_s + (r0+8)*260 + cc) = make_float2(c[mb][n8][2], c[mb][n8][3]);
            }
    }
    __syncthreads();

    // --- 128-step local scan along rows, one column per thread (256 threads) ---
    if (tid < 256){
        int s = tid;
        float cf = g_coeff[s];
        float st = 0.f;
        float pre[8];
        #pragma unroll
        for (int j = 0; j < 8; j++) pre[j] = U_s[j*260 + s];
        for (int r0 = 0; r0 < TM_; r0 += 8){
            float cur[8];
            #pragma unroll
            for (int j = 0; j < 8; j++) cur[j] = pre[j];
            if (r0 + 8 < TM_){
                #pragma unroll
                for (int j = 0; j < 8; j++) pre[j] = U_s[(r0+8+j)*260 + s];
            }
            #pragma unroll
            for (int j = 0; j < 8; j++){
                st = fmaf(cf, st, cur[j]);
                U_s[(r0+j)*260 + s] = st;
            }
        }
        int b = m0 >> 12, seg = (m0 >> 7) & (NSEG-1);
        g_cl[(b*NSEG + seg)*S_ + s] = st;
    }
    __syncthreads();

    // --- write local states to global ---
    #pragma unroll
    for (int j = 0; j < 16; j++){
        int c0 = 4*(qq + 4*j);
        float4 v = *(const float4*)(U_s + mr*260 + c0);
        *(float4*)(g_u + (size_t)(m0 + mr)*S_ + c0) = v;
    }
}

// ---------------- K2b: carry chain across segments ----------------
__global__ void k2b(const float* __restrict__ st0, float* __restrict__ fin)
{
    int s = threadIdx.x, b = blockIdx.x;
    float cseg = g_P[(SEGL-1)*S_ + s];   // coeff^SEGL
    float ci  = st0[b*S_ + s];
    const float* cl = g_cl + (size_t)b*NSEG*S_ + s;
    float*       cp = g_ci + (size_t)b*NSEG*S_ + s;
    float nxt = cl[0];
    #pragma unroll 1
    for (int seg = 0; seg < NSEG; seg++){
        float cur = nxt;
        if (seg + 1 < NSEG) nxt = cl[(seg+1)*S_];
        cp[seg*S_] = ci;
        ci = fmaf(cseg, ci, cur);
    }
    fin[b*S_ + s] = ci;
}

// ---------------- K3: readout GEMM + gelu + output GEMM + residual ----------------
__global__ void __launch_bounds__(512, 1)
k3(const float* __restrict__ x, const float* __restrict__ nw, const float* __restrict__ nb,
   const float* __restrict__ dir, const float* __restrict__ ob, float* __restrict__ y)
{
    extern __shared__ __align__(16) char smraw[];
    __nv_bfloat16* Ah = (__nv_bfloat16*)smraw;
    __nv_bfloat16* Al = Ah + TM_*AST;
    __nv_bfloat16* Bh = Al + TM_*AST;
    __nv_bfloat16* Bl = Bh + 256*BST;
    float* w_s  = (float*)(Bl + 256*BST);
    float* b_s  = w_s + 256;
    float* d_s  = b_s + 256;
    float* o_s  = d_s + 256;
    float* mu_s = o_s + 256;
    float* rs_s = mu_s + TM_;

    const int tid = threadIdx.x;
    const int m0  = blockIdx.x * TM_;
    if (tid < 256){
        w_s[tid] = nw[tid]; b_s[tid] = nb[tid];
        d_s[tid] = dir[tid]; o_s[tid] = ob[tid];
    }
    if (tid < TM_){ mu_s[tid] = g_mu[m0 + tid]; rs_s[tid] = g_rs[m0 + tid]; }
    // (these are first read in epilogue 2, after gemm's internal barriers)

    // --- load states tile: local + P[j]*carry, split hi/lo into A ---
    const int mr = tid >> 2, qq = tid & 3;     // mr 0..127
    {
        int b = m0 >> 12, seg = (m0 >> 7) & (NSEG-1);
        const float* lrow = g_u + (size_t)(m0 + mr) * S_;
        const float* Prow = g_P + mr * S_;                 // j == row-in-tile
        const float* crow = g_ci + (size_t)(b*NSEG + seg) * S_;
        #pragma unroll
        for (int j = 0; j < 16; j++){
            int c0 = 4*(qq + 4*j);
            float4 lv = *(const float4*)(lrow + c0);
            float4 pv = *(const float4*)(Prow + c0);
            float4 cv = *(const float4*)(crow + c0);
            float f0 = fmaf(pv.x, cv.x, lv.x);
            float f1 = fmaf(pv.y, cv.y, lv.y);
            float f2 = fmaf(pv.z, cv.z, lv.z);
            float f3 = fmaf(pv.w, cv.w, lv.w);
            uint2 ph, pl;
            ph.x = pk2(f0, f1); ph.y = pk2(f2, f3);
            pl.x = pk2(f0 - bf_hi(f0), f1 - bf_hi(f1));
            pl.y = pk2(f2 - bf_hi(f2), f3 - bf_hi(f3));
            *(uint2*)(Ah + mr*AST + c0) = ph;
            *(uint2*)(Al + mr*AST + c0) = pl;
        }
    }

    float c[2][8][4];
    #pragma unroll
    for (int i = 0; i < 2; i++)
        #pragma unroll
        for (int j = 0; j < 8; j++)
            #pragma unroll
            for (int q = 0; q < 4; q++) c[i][j][q] = 0.f;

    // GEMM2: mixed = states @ W2^T
    gemm_bf16x3(Ah, Al, Bh, Bl, g_W2h, g_W2l, c, tid);

    // --- epilogue 2: + direct*x_norm, gelu, re-split into A ---
    const int lane = tid & 31, w = tid >> 5;
    const int m0w = (w >> 2) * 32, n0w = (w & 3) * 64;
    const int gg = lane >> 2, tg = lane & 3;
    #pragma unroll
    for (int mb = 0; mb < 2; mb++)
        #pragma unroll
        for (int n8 = 0; n8 < 8; n8++){
            int cc = n0w + n8*8 + 2*tg;
            float dw0 = d_s[cc], dw1 = d_s[cc+1];
            float ww0 = w_s[cc], ww1 = w_s[cc+1];
            float bb0 = b_s[cc], bb1 = b_s[cc+1];
            #pragma unroll
            for (int half = 0; half < 2; half++){
                int r = m0w + mb*16 + gg + half*8;
                float2 xv = *(const float2*)(x + (size_t)(m0 + r)*H_ + cc);
                float muv = mu_s[r], rsv = rs_s[r];
                float xn0 = (xv.x - muv) * rsv * ww0 + bb0;
                float xn1 = (xv.y - muv) * rsv * ww1 + bb1;
                float v0 = gelu_t(c[mb][n8][half*2+0] + dw0 * xn0);
                float v1 = gelu_t(c[mb][n8][half*2+1] + dw1 * xn1);
                *(u32*)(Ah + r*AST + cc) = pk2(v0, v1);
                *(u32*)(Al + r*AST + cc) = pk2(v0 - bf_hi(v0), v1 - bf_hi(v1));
            }
        }
    #pragma unroll
    for (int i = 0; i < 2; i++)
        #pragma unroll
        for (int j = 0; j < 8; j++)
            #pragma unroll
            for (int q = 0; q < 4; q++) c[i][j][q] = 0.f;

    // GEMM3: proj = gelu(mixed) @ W3^T
    gemm_bf16x3(Ah, Al, Bh, Bl, g_W3h, g_W3l, c, tid);

    // --- epilogue 3: y = x + proj + out_b ---
    #pragma unroll
    for (int mb = 0; mb < 2; mb++)
        #pragma unroll
        for (int n8 = 0; n8 < 8; n8++){
            int cc = n0w + n8*8 + 2*tg;
            float oo0 = o_s[cc], oo1 = o_s[cc+1];
            #pragma unroll
            for (int half = 0; half < 2; half++){
                int r = m0w + mb*16 + gg + half*8;
                float2 xv = *(const float2*)(x + (size_t)(m0 + r)*H_ + cc);
                float2 out;
                out.x = xv.x + c[mb][n8][half*2+0] + oo0;
                out.y = xv.y + c[mb][n8][half*2+1] + oo1;
                *(float2*)(y + (size_t)(m0 + r)*H_ + cc) = out;
            }
        }
}

// ---------------- launcher ----------------
extern "C" void kernel_launch(void* const* d_in, const int* in_sizes, int n_in,
                              void* d_out, int out_size)
{
    const float* x   = (const float*)d_in[0];   // [B,T,H]
    const float* st0 = (const float*)d_in[1];   // [B,S]
    const float* Win = (const float*)d_in[2];   // [S,H]
    const float* W2  = (const float*)d_in[3];   // [H,S]
    const float* dir = (const float*)d_in[4];   // [H]
    const float* ad  = (const float*)d_in[5];   // [S]
    const float* gd  = (const float*)d_in[6];   // [S]
    const float* dt  = (const float*)d_in[7];   // [S]
    const float* nw  = (const float*)d_in[8];   // [H]
    const float* nb  = (const float*)d_in[9];   // [H]
    const float* W3  = (const float*)d_in[10];  // [H,H]
    const float* ob  = (const float*)d_in[11];  // [H]

    float* y   = (float*)d_out;
    float* fin = y + (size_t)M_ * H_;

    const int SMEM1 = (TM_*AST*2 + 256*BST*2)*2 + (256+256)*4;
    const int SMEM3 = (TM_*AST*2 + 256*BST*2)*2 + (256*4 + TM_*2)*4;
    cudaFuncSetAttribute(k1, cudaFuncAttributeMaxDynamicSharedMemorySize, SMEM1);
    cudaFuncSetAttribute(k3, cudaFuncAttributeMaxDynamicSharedMemorySize, SMEM3);

    k0c<<<1, 256>>>(ad, gd, dt);
    k0w<<<256, 256>>>(Win, W2, W3);
    k1<<<M_/TM_, 512, SMEM1>>>(x, nw, nb);
    k2b<<<B_, 256>>>(st0, fin);
    k3<<<M_/TM_, 512, SMEM3>>>(x, nw, nb, dir, ob, y);
}

// round 7
// speedup vs baseline: 3.0022x; 1.2594x over previous
#include <cuda_runtime.h>
#include <cuda_fp16.h>

#define B_   32
#define T_   4096
#define H_   256
#define S_   256
#define M_   (B_*T_)      // 131072 rows
#define TM_  128          // M tile / segment length
#define NSEG 32           // segments per batch (T/TM_)
#define SEGL 128

// A tile smem: [128 rows][264 fp16]  (row-major, 528B stride: conflict-free ldmatrix)
#define AST 264
// B tile smem: [256 n][40 fp16]      (80B stride: conflict-free ldmatrix)
#define BST 40

// lo-plane scale: Bl stored as (w - hi) * 2^10; A scaled by 2^-10 for the correction mma
#define SCALE_F   1024.0f
#define INV_SC_H2 0x14001400u   // half2(2^-10, 2^-10)

// ---------------- scratch (static device globals) ----------------
__device__ float g_u[(size_t)M_ * S_];     // segment-LOCAL states (written by k1)
__device__ float g_mu[M_];
__device__ float g_rs[M_];
__device__ float g_coeff[S_];
__device__ float g_P[SEGL * S_];           // P[j][s] = coeff[s]^(j+1)
__device__ float g_cl[B_ * NSEG * S_];     // local segment-end states
__device__ float g_ci[B_ * NSEG * S_];     // true state entering each segment
__device__ __align__(16) __half g_W1h[S_*H_], g_W1l[S_*H_];
__device__ __align__(16) __half g_W2h[H_*S_], g_W2l[H_*S_];
__device__ __align__(16) __half g_W3h[H_*H_], g_W3l[H_*H_];

typedef unsigned int u32;

// ---------------- small helpers ----------------
__device__ __forceinline__ unsigned sptr(const void* p){
    return (unsigned)__cvta_generic_to_shared(p);
}
// pack two floats to half2: a -> low 16 bits (element at lower address), b -> high
__device__ __forceinline__ u32 pk2h(float a, float b){
    __half ha = __float2half_rn(a), hb = __float2half_rn(b);
    unsigned short ua = *reinterpret_cast<unsigned short*>(&ha);
    unsigned short ub = *reinterpret_cast<unsigned short*>(&hb);
    return (u32)ua | ((u32)ub << 16);
}
__device__ __forceinline__ u32 hscale(u32 a){   // packed half2 * 2^-10
    u32 r; asm("mul.rn.f16x2 %0, %1, %2;" : "=r"(r) : "r"(a), "r"(INV_SC_H2));
    return r;
}
__device__ __forceinline__ float gelu_t(float v){
    float v3 = v * v * v;
    float t  = tanhf(0.7978845608028654f * (v + 0.044715f * v3));
    return 0.5f * v * (1.0f + t);
}

__device__ __forceinline__ void ldsm4(u32 r[4], unsigned addr){
    asm volatile("ldmatrix.sync.aligned.m8n8.x4.shared.b16 {%0,%1,%2,%3}, [%4];"
        : "=r"(r[0]), "=r"(r[1]), "=r"(r[2]), "=r"(r[3]) : "r"(addr));
}
__device__ __forceinline__ void mma_hh(float c[4], const u32 a[4], u32 b0, u32 b1){
    asm volatile("mma.sync.aligned.m16n8k16.row.col.f32.f16.f16.f32 "
        "{%0,%1,%2,%3},{%4,%5,%6,%7},{%8,%9},{%0,%1,%2,%3};"
        : "+f"(c[0]), "+f"(c[1]), "+f"(c[2]), "+f"(c[3])
        : "r"(a[0]), "r"(a[1]), "r"(a[2]), "r"(a[3]), "r"(b0), "r"(b1));
}

// ---------------- fp16 2-pass GEMM core ----------------
// C[128m][256n] += A[128m][256k] @ W^T, W row-major [n][k].
// A single fp16; W pre-split: Wh = fp16(w), Wl = fp16((w - Wh)*2^10).
// C = Ah*Bh + (Ah*2^-10)*Bl  (exact cross-term recovery, no subnormal operands).
// 16 warps: warp grid 4(M)x4(N), warp tile 32x64. Accum c[mblk2][n8blk8][4].
// K streamed in 8 chunks of 32 through Bh/Bl smem; next chunk register-prefetched.
__device__ __forceinline__ void gemm_h2(
    const __half* Ah,
    __half* Bh, __half* Bl,
    const __half* __restrict__ Wh, const __half* __restrict__ Wl,
    float c[2][8][4], int tid)
{
    const int lane = tid & 31;
    const int w    = tid >> 5;            // 0..15
    const int m0w  = (w >> 2) * 32;
    const int n0w  = (w & 3) * 64;
    const int k4   = tid & 7;             // B-load: which 4-elem group along k
    const int nb   = tid >> 3;            // B-load: base n row (0..63)
    const int lrow = lane & 15;
    const int lc8  = (lane >> 4) * 8;

    const unsigned aAh = sptr(Ah + (m0w + lrow) * AST + lc8);
    const unsigned aBh = sptr(Bh + (n0w + lrow) * BST + lc8);
    const unsigned aBl = sptr(Bl + (n0w + lrow) * BST + lc8);

    // prefetch chunk 0 into registers
    uint2 ph[4], pl4[4];
    #pragma unroll
    for (int j = 0; j < 4; j++){
        int n = nb + 64*j;
        ph[j]  = *(const uint2*)(Wh + n*256 + k4*4);
        pl4[j] = *(const uint2*)(Wl + n*256 + k4*4);
    }

    for (int ch = 0; ch < 8; ch++){
        __syncthreads();   // prev compute done (B smem reusable); A visible (1st iter)
        #pragma unroll
        for (int j = 0; j < 4; j++){
            int n = nb + 64*j;
            *(uint2*)(Bh + n*BST + k4*4) = ph[j];
            *(uint2*)(Bl + n*BST + k4*4) = pl4[j];
        }
        __syncthreads();   // B chunk visible
        if (ch < 7){       // issue next chunk's loads; they retire during compute
            #pragma unroll
            for (int j = 0; j < 4; j++){
                int n = nb + 64*j;
                ph[j]  = *(const uint2*)(Wh + n*256 + (ch+1)*32 + k4*4);
                pl4[j] = *(const uint2*)(Wl + n*256 + (ch+1)*32 + k4*4);
            }
        }

        #pragma unroll
        for (int ks = 0; ks < 2; ks++){
            const int kA2 = (ch*32 + ks*16) * 2;   // byte offset in A rows
            const int kB2 = (ks*16) * 2;           // byte offset in B rows
            u32 ah[2][4], as_[2][4];
            ldsm4(ah[0], aAh + kA2);
            ldsm4(ah[1], aAh + 16*AST*2 + kA2);
            #pragma unroll
            for (int mb = 0; mb < 2; mb++)
                #pragma unroll
                for (int j = 0; j < 4; j++) as_[mb][j] = hscale(ah[mb][j]);
            #pragma unroll
            for (int g4 = 0; g4 < 4; g4++){        // 4 groups of n16
                u32 bh[4], bl[4];
                ldsm4(bh, aBh + g4*16*BST*2 + kB2);
                ldsm4(bl, aBl + g4*16*BST*2 + kB2);
                #pragma unroll
                for (int mb = 0; mb < 2; mb++){
                    // n-low block: B = {r0, r2}; n-high block: B = {r1, r3}
                    mma_hh(c[mb][g4*2  ], ah[mb],  bh[0], bh[2]);
                    mma_hh(c[mb][g4*2  ], as_[mb], bl[0], bl[2]);
                    mma_hh(c[mb][g4*2+1], ah[mb],  bh[1], bh[3]);
                    mma_hh(c[mb][g4*2+1], as_[mb], bl[1], bl[3]);
                }
            }
        }
    }
    __syncthreads();   // protect epilogue overlay writes into A (WAR across warps)
}

// ---------------- K0a: coefficients + power table ----------------
__global__ void k0c(const float* __restrict__ a, const float* __restrict__ g,
                    const float* __restrict__ dt)
{
    int s = threadIdx.x;
    double d   = (double)dt[s];
    double sp  = log1p(exp(-fabs(d))) + fmax(d, 0.0);
    double dts = sp + 1e-4;
    double gg  = (double)g[s];
    double spg = log1p(exp(-fabs(gg))) + fmax(gg, 0.0);
    double cf  = exp(-2.0 * spg * dts) * cos((double)a[s] * dts);
    g_coeff[s] = (float)cf;
    double p = 1.0;
    for (int j = 0; j < SEGL; j++){ p *= cf; g_P[j*S_ + s] = (float)p; }
}

// ---------------- K0b: weight hi + scaled-lo split ----------------
__global__ void k0w(const float* __restrict__ W1, const float* __restrict__ W2,
                    const float* __restrict__ W3)
{
    int i = blockIdx.x * 256 + threadIdx.x;
    float w; __half h;
    w = W1[i]; h = __float2half_rn(w); g_W1h[i] = h;
    g_W1l[i] = __float2half_rn((w - __half2float(h)) * SCALE_F);
    w = W2[i]; h = __float2half_rn(w); g_W2h[i] = h;
    g_W2l[i] = __float2half_rn((w - __half2float(h)) * SCALE_F);
    w = W3[i]; h = __float2half_rn(w); g_W3h[i] = h;
    g_W3l[i] = __float2half_rn((w - __half2float(h)) * SCALE_F);
}

// ---------------- K1: LN + input GEMM + 128-step local scan ----------------
// smem layout: [0, 133120) U_s overlay region, which also contains
//   Ah [0, 67584), Bh [67584, 88064), Bl [88064, 108544)  during the GEMM.
//   w_s/b_s live above 133120 (never overlaid).
__global__ void __launch_bounds__(512, 1)
k1(const float* __restrict__ x, const float* __restrict__ nw, const float* __restrict__ nb)
{
    extern __shared__ __align__(16) char smraw[];
    __half* Ah = (__half*)smraw;
    __half* Bh = Ah + TM_*AST;
    __half* Bl = Bh + 256*BST;
    float* U_s = (float*)smraw;               // overlay (stride 260)
    float* w_s = (float*)(smraw + 133120);
    float* b_s = w_s + 256;

    const int tid = threadIdx.x;
    const int m0  = blockIdx.x * TM_;
    if (tid < 256){ w_s[tid] = nw[tid]; b_s[tid] = nb[tid]; }

    // --- LayerNorm (mu/rs via shuffle; 4 threads per row) ---
    const int mr = tid >> 2, qq = tid & 3;     // mr 0..127
    const float4* xrow = (const float4*)(x + (size_t)(m0 + mr) * H_);
    float s1 = 0.f, s2 = 0.f;
    #pragma unroll
    for (int j = 0; j < 16; j++){
        float4 v = xrow[qq + 4*j];
        s1 += v.x + v.y + v.z + v.w;
        s2 += v.x*v.x + v.y*v.y + v.z*v.z + v.w*v.w;
    }
    s1 += __shfl_xor_sync(0xffffffffu, s1, 1);
    s2 += __shfl_xor_sync(0xffffffffu, s2, 1);
    s1 += __shfl_xor_sync(0xffffffffu, s1, 2);
    s2 += __shfl_xor_sync(0xffffffffu, s2, 2);
    float mu  = s1 * (1.0f / H_);
    float var = s2 * (1.0f / H_) - mu * mu;
    float rs  = rsqrtf(var + 1e-5f);
    if (qq == 0){ g_mu[m0 + mr] = mu; g_rs[m0 + mr] = rs; }

    // make w_s/b_s visible to ALL threads before the normalize loop
    __syncthreads();

    // --- normalize -> fp16 into A ---
    #pragma unroll
    for (int j = 0; j < 16; j++){
        int c0 = 4*(qq + 4*j);
        float4 v = xrow[qq + 4*j];
        float f0 = (v.x - mu) * rs * w_s[c0+0] + b_s[c0+0];
        float f1 = (v.y - mu) * rs * w_s[c0+1] + b_s[c0+1];
        float f2 = (v.z - mu) * rs * w_s[c0+2] + b_s[c0+2];
        float f3 = (v.w - mu) * rs * w_s[c0+3] + b_s[c0+3];
        uint2 ph;
        ph.x = pk2h(f0, f1); ph.y = pk2h(f2, f3);
        *(uint2*)(Ah + mr*AST + c0) = ph;
    }
    // (first __syncthreads inside gemm makes A visible before ldmatrix)

    float c[2][8][4];
    #pragma unroll
    for (int i = 0; i < 2; i++)
        #pragma unroll
        for (int j = 0; j < 8; j++)
            #pragma unroll
            for (int q = 0; q < 4; q++) c[i][j][q] = 0.f;

    gemm_h2(Ah, Bh, Bl, g_W1h, g_W1l, c, tid);

    // --- dump u into smem scratch (gemm ended with syncthreads) ---
    {
        const int lane = tid & 31, w = tid >> 5;
        const int m0w = (w >> 2) * 32, n0w = (w & 3) * 64;
        const int gg = lane >> 2, tg = lane & 3;
        #pragma unroll
        for (int mb = 0; mb < 2; mb++)
            #pragma unroll
            for (int n8 = 0; n8 < 8; n8++){
                int r0 = m0w + mb*16 + gg;
                int cc = n0w + n8*8 + 2*tg;
                *(float2*)(U_s + r0*260 + cc)     = make_float2(c[mb][n8][0], c[mb][n8][1]);
                *(float2*)(U_s + (r0+8)*260 + cc) = make_float2(c[mb][n8][2], c[mb][n8][3]);
            }
    }
    __syncthreads();

    // --- 128-step local scan along rows, one column per thread (256 threads) ---
    if (tid < 256){
        int s = tid;
        float cf = g_coeff[s];
        float st = 0.f;
        float pre[8];
        #pragma unroll
        for (int j = 0; j < 8; j++) pre[j] = U_s[j*260 + s];
        for (int r0 = 0; r0 < TM_; r0 += 8){
            float cur[8];
            #pragma unroll
            for (int j = 0; j < 8; j++) cur[j] = pre[j];
            if (r0 + 8 < TM_){
                #pragma unroll
                for (int j = 0; j < 8; j++) pre[j] = U_s[(r0+8+j)*260 + s];
            }
            #pragma unroll
            for (int j = 0; j < 8; j++){
                st = fmaf(cf, st, cur[j]);
                U_s[(r0+j)*260 + s] = st;
            }
        }
        int b = m0 >> 12, seg = (m0 >> 7) & (NSEG-1);
        g_cl[(b*NSEG + seg)*S_ + s] = st;
    }
    __syncthreads();

    // --- write local states to global ---
    #pragma unroll
    for (int j = 0; j < 16; j++){
        int c0 = 4*(qq + 4*j);
        float4 v = *(const float4*)(U_s + mr*260 + c0);
        *(float4*)(g_u + (size_t)(m0 + mr)*S_ + c0) = v;
    }
}

// ---------------- K2b: carry chain across segments (all loads up front) ----------------
__global__ void k2b(const float* __restrict__ st0, float* __restrict__ fin)
{
    int s = threadIdx.x, b = blockIdx.x;
    float cseg = g_P[(SEGL-1)*S_ + s];   // coeff^SEGL
    float ci  = st0[b*S_ + s];
    const float* cl = g_cl + (size_t)b*NSEG*S_ + s;
    float*       cp = g_ci + (size_t)b*NSEG*S_ + s;
    float v[NSEG];
    #pragma unroll
    for (int i = 0; i < NSEG; i++) v[i] = __ldcg(cl + (size_t)i*S_);
    #pragma unroll
    for (int seg = 0; seg < NSEG; seg++){
        cp[(size_t)seg*S_] = ci;
        ci = fmaf(cseg, ci, v[seg]);
    }
    fin[b*S_ + s] = ci;
}

// ---------------- K3: readout GEMM + gelu + output GEMM + residual ----------------
__global__ void __launch_bounds__(512, 1)
k3(const float* __restrict__ x, const float* __restrict__ nw, const float* __restrict__ nb,
   const float* __restrict__ dir, const float* __restrict__ ob, float* __restrict__ y)
{
    extern __shared__ __align__(16) char smraw[];
    __half* Ah = (__half*)smraw;
    __half* Bh = Ah + TM_*AST;
    __half* Bl = Bh + 256*BST;
    float* w_s  = (float*)(Bl + 256*BST);
    float* b_s  = w_s + 256;
    float* d_s  = b_s + 256;
    float* o_s  = d_s + 256;
    float* mu_s = o_s + 256;
    float* rs_s = mu_s + TM_;

    const int tid = threadIdx.x;
    const int m0  = blockIdx.x * TM_;
    if (tid < 256){
        w_s[tid] = nw[tid]; b_s[tid] = nb[tid];
        d_s[tid] = dir[tid]; o_s[tid] = ob[tid];
    }
    if (tid < TM_){ mu_s[tid] = g_mu[m0 + tid]; rs_s[tid] = g_rs[m0 + tid]; }
    // (these are first read in epilogue 2, after gemm's internal barriers)

    // --- load states tile: local + P[j]*carry -> fp16 into A ---
    const int mr = tid >> 2, qq = tid & 3;     // mr 0..127
    {
        int b = m0 >> 12, seg = (m0 >> 7) & (NSEG-1);
        const float* lrow = g_u + (size_t)(m0 + mr) * S_;
        const float* Prow = g_P + mr * S_;                 // j == row-in-tile
        const float* crow = g_ci + (size_t)(b*NSEG + seg) * S_;
        #pragma unroll
        for (int j = 0; j < 16; j++){
            int c0 = 4*(qq + 4*j);
            float4 lv = *(const float4*)(lrow + c0);
            float4 pv = *(const float4*)(Prow + c0);
            float4 cv = *(const float4*)(crow + c0);
            float f0 = fmaf(pv.x, cv.x, lv.x);
            float f1 = fmaf(pv.y, cv.y, lv.y);
            float f2 = fmaf(pv.z, cv.z, lv.z);
            float f3 = fmaf(pv.w, cv.w, lv.w);
            uint2 ph;
            ph.x = pk2h(f0, f1); ph.y = pk2h(f2, f3);
            *(uint2*)(Ah + mr*AST + c0) = ph;
        }
    }

    float c[2][8][4];
    #pragma unroll
    for (int i = 0; i < 2; i++)
        #pragma unroll
        for (int j = 0; j < 8; j++)
            #pragma unroll
            for (int q = 0; q < 4; q++) c[i][j][q] = 0.f;

    // GEMM2: mixed = states @ W2^T
    gemm_h2(Ah, Bh, Bl, g_W2h, g_W2l, c, tid);

    // --- epilogue 2: + direct*x_norm, gelu -> fp16 back into A ---
    const int lane = tid & 31, w = tid >> 5;
    const int m0w = (w >> 2) * 32, n0w = (w & 3) * 64;
    const int gg = lane >> 2, tg = lane & 3;
    #pragma unroll
    for (int mb = 0; mb < 2; mb++)
        #pragma unroll
        for (int n8 = 0; n8 < 8; n8++){
            int cc = n0w + n8*8 + 2*tg;
            float dw0 = d_s[cc], dw1 = d_s[cc+1];
            float ww0 = w_s[cc], ww1 = w_s[cc+1];
            float bb0 = b_s[cc], bb1 = b_s[cc+1];
            #pragma unroll
            for (int half = 0; half < 2; half++){
                int r = m0w + mb*16 + gg + half*8;
                float2 xv = *(const float2*)(x + (size_t)(m0 + r)*H_ + cc);
                float muv = mu_s[r], rsv = rs_s[r];
                float xn0 = (xv.x - muv) * rsv * ww0 + bb0;
                float xn1 = (xv.y - muv) * rsv * ww1 + bb1;
                float v0 = gelu_t(c[mb][n8][half*2+0] + dw0 * xn0);
                float v1 = gelu_t(c[mb][n8][half*2+1] + dw1 * xn1);
                *(u32*)(Ah + r*AST + cc) = pk2h(v0, v1);
            }
        }
    #pragma unroll
    for (int i = 0; i < 2; i++)
        #pragma unroll
        for (int j = 0; j < 8; j++)
            #pragma unroll
            for (int q = 0; q < 4; q++) c[i][j][q] = 0.f;

    // GEMM3: proj = gelu(mixed) @ W3^T
    gemm_h2(Ah, Bh, Bl, g_W3h, g_W3l, c, tid);

    // --- epilogue 3: y = x + proj + out_b ---
    #pragma unroll
    for (int mb = 0; mb < 2; mb++)
        #pragma unroll
        for (int n8 = 0; n8 < 8; n8++){
            int cc = n0w + n8*8 + 2*tg;
            float oo0 = o_s[cc], oo1 = o_s[cc+1];
            #pragma unroll
            for (int half = 0; half < 2; half++){
                int r = m0w + mb*16 + gg + half*8;
                float2 xv = *(const float2*)(x + (size_t)(m0 + r)*H_ + cc);
                float2 out;
                out.x = xv.x + c[mb][n8][half*2+0] + oo0;
                out.y = xv.y + c[mb][n8][half*2+1] + oo1;
                *(float2*)(y + (size_t)(m0 + r)*H_ + cc) = out;
            }
        }
}

// ---------------- launcher ----------------
extern "C" void kernel_launch(void* const* d_in, const int* in_sizes, int n_in,
                              void* d_out, int out_size)
{
    const float* x   = (const float*)d_in[0];   // [B,T,H]
    const float* st0 = (const float*)d_in[1];   // [B,S]
    const float* Win = (const float*)d_in[2];   // [S,H]
    const float* W2  = (const float*)d_in[3];   // [H,S]
    const float* dir = (const float*)d_in[4];   // [H]
    const float* ad  = (const float*)d_in[5];   // [S]
    const float* gd  = (const float*)d_in[6];   // [S]
    const float* dt  = (const float*)d_in[7];   // [S]
    const float* nw  = (const float*)d_in[8];   // [H]
    const float* nb  = (const float*)d_in[9];   // [H]
    const float* W3  = (const float*)d_in[10];  // [H,H]
    const float* ob  = (const float*)d_in[11];  // [H]

    float* y   = (float*)d_out;
    float* fin = y + (size_t)M_ * H_;

    const int SMEM1 = 133120 + 2*256*4;                       // U_s overlay + w/b
    const int SMEM3 = (TM_*AST + 2*256*BST)*2 + (256*4 + TM_*2)*4;
    cudaFuncSetAttribute(k1, cudaFuncAttributeMaxDynamicSharedMemorySize, SMEM1);
    cudaFuncSetAttribute(k3, cudaFuncAttributeMaxDynamicSharedMemorySize, SMEM3);

    k0c<<<1, 256>>>(ad, gd, dt);
    k0w<<<256, 256>>>(Win, W2, W3);
    k1<<<M_/TM_, 512, SMEM1>>>(x, nw, nb);
    k2b<<<B_, 256>>>(st0, fin);
    k3<<<M_/TM_, 512, SMEM3>>>(x, nw, nb, dir, ob, y);
}